// round 15
// baseline (speedup 1.0000x reference)
#include <cuda_runtime.h>
#include <cuda_bf16.h>
#include <cstdint>
#include <math.h>

typedef unsigned int u32;
typedef unsigned long long u64;

// ---------------- problem constants ----------------
#define BB 4
#define TT 2048
#define DD 1024
#define KK 512
#define KR 16

// ---------------- fp32 scratch ----------------
__device__ float g_Q[BB*TT*DD];
__device__ float g_V[BB*TT*DD];
__device__ float g_scores[(long)BB*TT*TT];
__device__ float g_byp[BB*TT*DD];
__device__ float g_L[BB*TT*KK];
__device__ float g_G[BB*TT*KK];
__device__ float g_Rw[BB*TT*KK];
__device__ float g_Vagg[BB*KK*DD];
__device__ float g_SV[BB*KK*KK];
__device__ float g_P2[BB*KK*KK];
__device__ float g_R4[BB*KK*KK];
__device__ float g_Acov[KK*KK];
__device__ float g_Xa[KK*KK];
__device__ float g_Xb[KK*KK];
__device__ float g_Yt[KK*KK];
__device__ float g_Wnc0[KK];
__device__ float g_w[TT];
__device__ float g_snorm[KK];
__device__ float g_nov[BB*TT];
__device__ float g_p[BB*TT];
__device__ float g_SnextScratch[BB*KK*DD];

// ---------------- bf16 split scratch ----------------
__device__ __nv_bfloat16 g_xh[BB*TT*DD];
__device__ __nv_bfloat16 g_xl[BB*TT*DD];
__device__ __nv_bfloat16 g_Qh[BB*TT*DD];
__device__ __nv_bfloat16 g_Ql[BB*TT*DD];
__device__ __nv_bfloat16 g_Vh[BB*TT*DD];
__device__ __nv_bfloat16 g_Vl[BB*TT*DD];
__device__ __nv_bfloat16 g_Vth[BB*DD*TT];
__device__ __nv_bfloat16 g_Vtl[BB*DD*TT];
__device__ __nv_bfloat16 g_Ph[(long)BB*TT*TT];
__device__ __nv_bfloat16 g_Pl[(long)BB*TT*TT];
__device__ __nv_bfloat16 g_Sh[KK*DD];
__device__ __nv_bfloat16 g_Sl[KK*DD];
__device__ __nv_bfloat16 g_Sth[DD*KK];
__device__ __nv_bfloat16 g_Stl[DD*KK];
__device__ __nv_bfloat16 g_Wqh[DD*DD];
__device__ __nv_bfloat16 g_Wql[DD*DD];
__device__ __nv_bfloat16 g_Wvh[DD*DD];
__device__ __nv_bfloat16 g_Wvl[DD*DD];
__device__ __nv_bfloat16 g_WnTh[KK*DD];
__device__ __nv_bfloat16 g_WnTl[KK*DD];
__device__ __nv_bfloat16 g_RwTh[BB*KK*TT];
__device__ __nv_bfloat16 g_RwTl[BB*KK*TT];
__device__ __nv_bfloat16 g_P2h[BB*KK*KK];
__device__ __nv_bfloat16 g_P2l[BB*KK*KK];
// chain operand forms
__device__ __nv_bfloat16 g_ACth[KK*KK];
__device__ __nv_bfloat16 g_ACtl[KK*KK];
__device__ __nv_bfloat16 g_Yh[KK*KK];
__device__ __nv_bfloat16 g_Yl[KK*KK];
__device__ __nv_bfloat16 g_Xah[KK*KK];
__device__ __nv_bfloat16 g_Xal[KK*KK];
__device__ __nv_bfloat16 g_Xath[KK*KK];
__device__ __nv_bfloat16 g_Xatl[KK*KK];
__device__ __nv_bfloat16 g_Xbh[KK*KK];
__device__ __nv_bfloat16 g_Xbl[KK*KK];
__device__ __nv_bfloat16 g_Xbth[KK*KK];
__device__ __nv_bfloat16 g_Xbtl[KK*KK];
__device__ __nv_bfloat16 g_VAGh[BB*KK*DD];
__device__ __nv_bfloat16 g_VAGl[BB*KK*DD];
__device__ __nv_bfloat16 g_SVh[BB*KK*KK];
__device__ __nv_bfloat16 g_SVl[BB*KK*KK];
__device__ __nv_bfloat16 g_R4h[BB*KK*KK];
__device__ __nv_bfloat16 g_R4l[BB*KK*KK];

// ---------------- reductions ----------------
__device__ __forceinline__ float warpReduceSum(float v){
  #pragma unroll
  for (int o=16;o;o>>=1) v += __shfl_xor_sync(0xffffffffu, v, o);
  return v;
}
__device__ __forceinline__ float warpReduceMax(float v){
  #pragma unroll
  for (int o=16;o;o>>=1) v = fmaxf(v, __shfl_xor_sync(0xffffffffu, v, o));
  return v;
}
__device__ float blockReduceSum(float v){
  __shared__ float sh[33];
  int lane = threadIdx.x & 31, wid = threadIdx.x >> 5, nw = blockDim.x >> 5;
  v = warpReduceSum(v);
  __syncthreads();
  if (lane==0) sh[wid]=v;
  __syncthreads();
  if (wid==0){
    float r = (lane<nw)? sh[lane] : 0.f;
    r = warpReduceSum(r);
    if (lane==0) sh[32]=r;
  }
  __syncthreads();
  return sh[32];
}
__device__ float blockReduceMax(float v){
  __shared__ float sh[33];
  int lane = threadIdx.x & 31, wid = threadIdx.x >> 5, nw = blockDim.x >> 5;
  v = warpReduceMax(v);
  __syncthreads();
  if (lane==0) sh[wid]=v;
  __syncthreads();
  if (wid==0){
    float r = (lane<nw)? sh[lane] : -INFINITY;
    r = warpReduceMax(r);
    if (lane==0) sh[32]=r;
  }
  __syncthreads();
  return sh[32];
}

// ================= mma.sync helpers =================
__device__ __forceinline__ void ldsm4(u32& r0, u32& r1, u32& r2, u32& r3, u32 saddr){
  asm volatile("ldmatrix.sync.aligned.m8n8.x4.shared.b16 {%0,%1,%2,%3}, [%4];"
    : "=r"(r0), "=r"(r1), "=r"(r2), "=r"(r3) : "r"(saddr));
}
__device__ __forceinline__ void mma16816(float* c, const u32* a, const u32* b){
  asm volatile(
    "mma.sync.aligned.m16n8k16.row.col.f32.bf16.bf16.f32 "
    "{%0,%1,%2,%3}, {%4,%5,%6,%7}, {%8,%9}, {%0,%1,%2,%3};"
    : "+f"(c[0]), "+f"(c[1]), "+f"(c[2]), "+f"(c[3])
    : "r"(a[0]), "r"(a[1]), "r"(a[2]), "r"(a[3]), "r"(b[0]), "r"(b[1]));
}
__device__ __forceinline__ void cpasync16(u32 dst, const void* src){
  asm volatile("cp.async.cg.shared.global [%0], [%1], 16;" :: "r"(dst), "l"(src));
}

// epilogue codes
#define EPI_PLAIN 0
#define EPI_BIAS  1
#define EPI_COV   2
#define EPI_RW    3
#define EPI_NS    4
#define EPI_SNEXT 5
#define EPI_RSUB  6
#define EPI_ADD   7

// 128x64 tile, 256 threads, 2 CTAs/SM geometry.
#define ROWB 144
#define ARR_A (128*ROWB)                 // 18432 B per A operand array
#define ARR_BB (64*ROWB)                 // 9216 B per B operand array
#define ST_B  (2*ARR_A + 2*ARR_BB)       // 55296 B per pipeline stage
#define MM_SMEM (2*ST_B)                 // 110592 B dynamic -> 2 CTAs/SM

// ================= bf16x3 NT GEMM via mma.sync: C[M,N] = A[M,K]*B[N,K]^T ====
// 256 thr (4m x 2n warps), 128x64 tile, BK=64, 2-stage cp.async pipeline,
// frag double-buffer + term-major MMA order. 2 CTAs/SM overlap barriers.
__global__ void __launch_bounds__(256)
gemm_mm(const __nv_bfloat16* Ah, const __nv_bfloat16* Al, int lda, long sA,
        const __nv_bfloat16* Bh, const __nv_bfloat16* Bl, int ldb, long sB,
        float* C, int ldc, long sC,
        __nv_bfloat16* Coh, __nv_bfloat16* Col,
        __nv_bfloat16* Cth, __nv_bfloat16* Ctl, int ldt,
        int Kd, int epi, int cskip, int klim, float alpha,
        const float* bias, const float* aux1, long s1,
        const float* aux2, long s2, const float* rowv)
{
  // causal skip for 128-row x 64-col blocks: fully masked iff 64*bx > 128*by+127
  if (cskip && (int)blockIdx.x > 2*(int)blockIdx.y + 1) return;
  extern __shared__ __nv_bfloat16 dynsm[];

  const int tid  = threadIdx.x;
  const int lane = tid & 31;
  const int warp = tid >> 5;            // 0..7
  const int wm = warp >> 1, wn = warp & 1;   // 4m x 2n warp grid
  const int m0 = blockIdx.y*128, n0 = blockIdx.x*64;
  const long z = blockIdx.z;
  Ah += z*sA; Al += z*sA; Bh += z*sB; Bl += z*sB; C += z*sC;
  const float* ax1 = aux1 ? aux1 + z*s1 : aux1;
  const float* ax2 = aux2 ? aux2 + z*s2 : aux2;

  const u32 sm0 = (u32)__cvta_generic_to_shared(dynsm);

  float acc[2][4][4];
  #pragma unroll
  for (int i=0;i<2;i++)
    #pragma unroll
    for (int j=0;j<4;j++)
      #pragma unroll
      for (int q=0;q<4;q++) acc[i][j][q] = 0.f;

  const int kend = klim ? min(Kd, m0+128) : Kd;
  const int nch  = kend >> 6;

  // loaders: A tile 128x64 (4 cpasync/thread/array), B tile 64x64 (2/thread/array)
  const int lrA = tid >> 1;             // 0..127
  const int lqA = (tid & 1) * 32;       // 0 or 32 elements
  const int lrB = tid >> 2;             // 0..63
  const int lqB = (tid & 3) * 16;       // 0,16,32,48 elements
  const __nv_bfloat16* gA_h = Ah + (long)(m0+lrA)*lda + lqA;
  const __nv_bfloat16* gA_l = Al + (long)(m0+lrA)*lda + lqA;
  const __nv_bfloat16* gB_h = Bh + (long)(n0+lrB)*ldb + lqB;
  const __nv_bfloat16* gB_l = Bl + (long)(n0+lrB)*ldb + lqB;
  const u32 dA0 = sm0 + lrA*ROWB + lqA*2;
  const u32 dB0 = sm0 + 2*ARR_A + lrB*ROWB + lqB*2;

  auto issue_chunk = [&](int cc, int ss){
    int k0 = cc << 6;
    u32 dA = dA0 + ss*ST_B;
    cpasync16(dA,      gA_h + k0);
    cpasync16(dA + 16, gA_h + k0 + 8);
    cpasync16(dA + 32, gA_h + k0 + 16);
    cpasync16(dA + 48, gA_h + k0 + 24);
    cpasync16(dA +      ARR_A, gA_l + k0);
    cpasync16(dA + 16 + ARR_A, gA_l + k0 + 8);
    cpasync16(dA + 32 + ARR_A, gA_l + k0 + 16);
    cpasync16(dA + 48 + ARR_A, gA_l + k0 + 24);
    u32 dB = dB0 + ss*ST_B;
    cpasync16(dB,      gB_h + k0);
    cpasync16(dB + 16, gB_h + k0 + 8);
    cpasync16(dB +      ARR_BB, gB_l + k0);
    cpasync16(dB + 16 + ARR_BB, gB_l + k0 + 8);
    asm volatile("cp.async.commit_group;" ::: "memory");
  };

  issue_chunk(0, 0);

  u32 fa_h[2][2][4], fa_l[2][2][4];
  u32 fb_h[2][4][2], fb_l[2][4][2];

  const int ga  = lane >> 3;
  const int ar_ = (ga & 1)*8 + (lane & 7);
  const int br_ = (ga >> 1)*8 + (lane & 7);

  for (int c=0; c<nch; c++){
    asm volatile("cp.async.wait_group 0;" ::: "memory");
    __syncthreads();
    if (c+1 < nch) issue_chunk(c+1, (c+1)&1);

    const u32 sbase = sm0 + (c&1)*ST_B;

    {
      int ac = (ga >> 1)*8;
      #pragma unroll
      for (int mt=0; mt<2; mt++){
        u32 sa = sbase + (wm*32 + mt*16 + ar_)*ROWB + ac*2;
        ldsm4(fa_h[0][mt][0], fa_h[0][mt][1], fa_h[0][mt][2], fa_h[0][mt][3], sa);
        ldsm4(fa_l[0][mt][0], fa_l[0][mt][1], fa_l[0][mt][2], fa_l[0][mt][3], sa + ARR_A);
      }
      int bc = (ga & 1)*8;
      #pragma unroll
      for (int pr=0; pr<2; pr++){
        u32 sb = sbase + 2*ARR_A + (wn*32 + pr*16 + br_)*ROWB + bc*2;
        ldsm4(fb_h[0][pr*2][0], fb_h[0][pr*2][1], fb_h[0][pr*2+1][0], fb_h[0][pr*2+1][1], sb);
        ldsm4(fb_l[0][pr*2][0], fb_l[0][pr*2][1], fb_l[0][pr*2+1][0], fb_l[0][pr*2+1][1], sb + ARR_BB);
      }
    }

    #pragma unroll
    for (int i=0; i<4; i++){
      const int cb = i & 1, nb = cb ^ 1;
      if (i < 3){
        int kk = (i+1) << 4;
        int ac = kk + (ga >> 1)*8;
        #pragma unroll
        for (int mt=0; mt<2; mt++){
          u32 sa = sbase + (wm*32 + mt*16 + ar_)*ROWB + ac*2;
          ldsm4(fa_h[nb][mt][0], fa_h[nb][mt][1], fa_h[nb][mt][2], fa_h[nb][mt][3], sa);
          ldsm4(fa_l[nb][mt][0], fa_l[nb][mt][1], fa_l[nb][mt][2], fa_l[nb][mt][3], sa + ARR_A);
        }
        int bc = kk + (ga & 1)*8;
        #pragma unroll
        for (int pr=0; pr<2; pr++){
          u32 sb = sbase + 2*ARR_A + (wn*32 + pr*16 + br_)*ROWB + bc*2;
          ldsm4(fb_h[nb][pr*2][0], fb_h[nb][pr*2][1], fb_h[nb][pr*2+1][0], fb_h[nb][pr*2+1][1], sb);
          ldsm4(fb_l[nb][pr*2][0], fb_l[nb][pr*2][1], fb_l[nb][pr*2+1][0], fb_l[nb][pr*2+1][1], sb + ARR_BB);
        }
      }
      #pragma unroll
      for (int mt=0; mt<2; mt++)
        #pragma unroll
        for (int nt=0; nt<4; nt++)
          mma16816(acc[mt][nt], fa_h[cb][mt], fb_h[cb][nt]);
      #pragma unroll
      for (int mt=0; mt<2; mt++)
        #pragma unroll
        for (int nt=0; nt<4; nt++)
          mma16816(acc[mt][nt], fa_h[cb][mt], fb_l[cb][nt]);
      #pragma unroll
      for (int mt=0; mt<2; mt++)
        #pragma unroll
        for (int nt=0; nt<4; nt++)
          mma16816(acc[mt][nt], fa_l[cb][mt], fb_h[cb][nt]);
    }
  }

  // ---- epilogue ----
  const int gr = lane >> 2;
  const int tc = (lane & 3) * 2;
  #pragma unroll
  for (int mt=0; mt<2; mt++){
    #pragma unroll
    for (int h=0; h<2; h++){
      int r = m0 + wm*32 + mt*16 + h*8 + gr;
      float* Crow = C + (long)r*ldc;
      #pragma unroll
      for (int nt=0; nt<4; nt++){
        int ccol = n0 + wn*32 + nt*8 + tc;
        float v0 = acc[mt][nt][h*2], v1 = acc[mt][nt][h*2+1];
        if (epi == EPI_PLAIN){
          v0 *= alpha; v1 *= alpha;
        } else if (epi == EPI_BIAS){
          v0 += bias[ccol]; v1 += bias[ccol+1];
        } else if (epi == EPI_RW){
          float a1r = ax1[r], rv = rowv[r & (TT-1)];
          float x0 = v0 + a1r*ax2[ccol]   + bias[ccol];
          float x1 = v1 + a1r*ax2[ccol+1] + bias[ccol+1];
          v0 = rv / (1.f + expf(-x0));
          v1 = rv / (1.f + expf(-x1));
        } else if (epi == EPI_SNEXT){
          v0 = 0.99f*ax1[(long)r*ldc + ccol]   + 0.1f*(ax2[(long)r*ldc + ccol]   - v0);
          v1 = 0.99f*ax1[(long)r*ldc + ccol+1] + 0.1f*(ax2[(long)r*ldc + ccol+1] - v1);
        } else if (epi == EPI_COV){
          if (r == ccol)   v0 += 1e-5f;
          if (r == ccol+1) v1 += 1e-5f;
        } else if (epi == EPI_NS){
          v0 = 2.f*ax1[(long)r*ldc + ccol]   - v0;
          v1 = 2.f*ax1[(long)r*ldc + ccol+1] - v1;
        } else if (epi == EPI_RSUB){
          v0 = ax1[(long)r*ldc + ccol]   - v0;
          v1 = ax1[(long)r*ldc + ccol+1] - v1;
        } else if (epi == EPI_ADD){
          v0 = ax1[(long)r*ldc + ccol]   + v0;
          v1 = ax1[(long)r*ldc + ccol+1] + v1;
        }
        *(float2*)(Crow + ccol) = make_float2(v0, v1);
        __nv_bfloat16 h0, h1, l0, l1;
        if (Coh || Cth){
          h0 = __float2bfloat16(v0);
          h1 = __float2bfloat16(v1);
          l0 = __float2bfloat16(v0 - __bfloat162float(h0));
          l1 = __float2bfloat16(v1 - __bfloat162float(h1));
        }
        if (Coh){
          *(__nv_bfloat162*)(Coh + z*sC + (long)r*ldc + ccol) = __halves2bfloat162(h0, h1);
          *(__nv_bfloat162*)(Col + z*sC + (long)r*ldc + ccol) = __halves2bfloat162(l0, l1);
        }
        if (Cth){
          Cth[z*sC + (long)ccol*ldt + r]     = h0;
          Ctl[z*sC + (long)ccol*ldt + r]     = l0;
          Cth[z*sC + (long)(ccol+1)*ldt + r] = h1;
          Ctl[z*sC + (long)(ccol+1)*ldt + r] = l1;
        }
      }
    }
  }
}

// ---------------- elementwise / prep kernels ----------------
__global__ void split_kern(const float* __restrict__ X, __nv_bfloat16* __restrict__ H,
                           __nv_bfloat16* __restrict__ Lo, long n){
  long i = (long)blockIdx.x*256 + threadIdx.x;
  if (i < n){
    float v = X[i];
    __nv_bfloat16 h = __float2bfloat16(v);
    H[i] = h;
    Lo[i] = __float2bfloat16(v - __bfloat162float(h));
  }
}

__global__ void tsplit_kern(const float* __restrict__ X, __nv_bfloat16* __restrict__ TH,
                            __nv_bfloat16* __restrict__ TL, int R, int Cc){
  __shared__ float tile[32][33];
  const float* Xz = X + (long)blockIdx.z*R*Cc;
  __nv_bfloat16* THz = TH + (long)blockIdx.z*R*Cc;
  __nv_bfloat16* TLz = TL + (long)blockIdx.z*R*Cc;
  int c0 = blockIdx.x*32, r0 = blockIdx.y*32;
  int tx = threadIdx.x, ty = threadIdx.y;
  for (int i=ty; i<32; i+=8)
    tile[i][tx] = Xz[(long)(r0+i)*Cc + c0 + tx];
  __syncthreads();
  for (int i=ty; i<32; i+=8){
    float v = tile[tx][i];
    __nv_bfloat16 h = __float2bfloat16(v);
    long o = (long)(c0+i)*R + r0 + tx;
    THz[o] = h;
    TLz[o] = __float2bfloat16(v - __bfloat162float(h));
  }
}

__global__ void pack_wn_k(const float* __restrict__ Wn, __nv_bfloat16* __restrict__ H,
                          __nv_bfloat16* __restrict__ Lo, float* __restrict__ c0){
  long i = (long)blockIdx.x*256 + threadIdx.x;
  if (i < (long)KK*DD){
    int k = (int)(i >> 10), d = (int)(i & 1023);
    float v = Wn[(long)k*(DD+1) + 1 + d];
    __nv_bfloat16 h = __float2bfloat16(v);
    H[i] = h;
    Lo[i] = __float2bfloat16(v - __bfloat162float(h));
    if (d==0) c0[k] = Wn[(long)k*(DD+1)];
  }
}

__global__ void prep_w_k(float* __restrict__ w){
  int t = blockIdx.x*256 + threadIdx.x;
  if (t < TT){
    double z = (1.0 - pow(0.99, (double)TT)) / 0.01;
    w[t] = (float)(pow(0.99, (double)(TT-1-t)) / z);
  }
}

__global__ void snorm_k(const float* __restrict__ S, float* __restrict__ sn){
  int k = blockIdx.x*8 + (threadIdx.x>>5);
  int lane = threadIdx.x & 31;
  float s = 0.f;
  const float4* row = (const float4*)(S + (long)k*DD);
  for (int i=lane; i<DD/4; i+=32){ float4 a = row[i]; s += a.x*a.x+a.y*a.y+a.z*a.z+a.w*a.w; }
  s = warpReduceSum(s);
  if (lane==0) sn[k] = fmaxf(sqrtf(s), 1e-8f);
}

__global__ void init_x0_k(float* __restrict__ X,
                          __nv_bfloat16* __restrict__ Xh, __nv_bfloat16* __restrict__ Xl,
                          __nv_bfloat16* __restrict__ Xth, __nv_bfloat16* __restrict__ Xtl,
                          float alpha){
  int i = blockIdx.x*256 + threadIdx.x;
  int r = i >> 9, c = i & (KK-1);
  float v = (r==c) ? alpha : 0.f;
  X[i] = v;
  __nv_bfloat16 h = __float2bfloat16(v);
  __nv_bfloat16 l = __float2bfloat16(v - __bfloat162float(h));
  Xh[i] = h; Xl[i] = l;
  long t = (long)c*KK + r;
  Xth[t] = h; Xtl[t] = l;
}

__global__ void instr_k(const float* __restrict__ Q, const float* __restrict__ Wm,
                        const float* __restrict__ Wmb, float* __restrict__ p){
  int m = blockIdx.x*8 + (threadIdx.x>>5);
  int lane = threadIdx.x & 31;
  const float4* q = (const float4*)(Q + (long)m*DD);
  const float4* w = (const float4*)Wm;
  float acc = 0.f;
  for (int i=lane; i<DD/4; i+=32){
    float4 a=q[i], b=w[i];
    acc += a.x*b.x + a.y*b.y + a.z*b.z + a.w*b.w;
  }
  acc = warpReduceSum(acc);
  if (lane==0){
    p[m] = 1.f/(1.f+expf(-(acc + Wmb[0])));
  }
}

__global__ void novelty_k(const float* __restrict__ V, const float* __restrict__ G,
                          const float* __restrict__ sn, float* __restrict__ nov){
  int m = blockIdx.x;
  float s = 0.f;
  for (int d=threadIdx.x; d<DD; d+=256){ float x = V[(long)m*DD+d]; s += x*x; }
  s = blockReduceSum(s);
  float vn = fmaxf(sqrtf(s), 1e-8f);
  float mx = -INFINITY;
  for (int k=threadIdx.x; k<KK; k+=256) mx = fmaxf(mx, G[(long)m*KK+k] / (vn*sn[k]));
  mx = blockReduceMax(mx);
  if (threadIdx.x==0) nov[m] = 1.f - mx;
}

__global__ void softmax_k(const float* __restrict__ sc,
                          __nv_bfloat16* __restrict__ Ph, __nv_bfloat16* __restrict__ Pl){
  int m = blockIdx.x;
  int q = m & (TT-1);
  const float* row = sc + (long)m*TT;
  __nv_bfloat16* ph = Ph + (long)m*TT;
  __nv_bfloat16* pl = Pl + (long)m*TT;
  int len = q+1;
  int kend = ((q>>7)+1) << 7;
  float mx = -INFINITY;
  for (int k=threadIdx.x; k<len; k+=256) mx = fmaxf(mx, row[k]);
  mx = blockReduceMax(mx);
  float s = 0.f;
  for (int k=threadIdx.x; k<len; k+=256) s += expf(row[k]-mx);
  s = blockReduceSum(s);
  float inv = 1.f/s;
  for (int k=threadIdx.x; k<kend; k+=256){
    float p = (k<len) ? expf(row[k]-mx)*inv : 0.f;
    __nv_bfloat16 h = __float2bfloat16(p);
    ph[k] = h;
    pl[k] = __float2bfloat16(p - __bfloat162float(h));
  }
}

__global__ void __launch_bounds__(128)
topk_k(const float* __restrict__ L, const float* __restrict__ S,
       const float* __restrict__ p_, const float* __restrict__ byp,
       float* __restrict__ out){
  __shared__ float ls[KK];
  __shared__ float tv[KR];
  __shared__ int   ti[KR];
  __shared__ float wv[4];
  __shared__ int   wi[4];
  __shared__ float probs[KR];
  int m = blockIdx.x, tid = threadIdx.x;
  for (int k=tid; k<KK; k+=128) ls[k] = L[(long)m*KK + k];
  __syncthreads();
  for (int it=0; it<KR; it++){
    float bv = -INFINITY; int bi = 0;
    #pragma unroll
    for (int u=0; u<KK/128; u++){
      int k = tid + u*128;
      float x = ls[k];
      if (x > bv){ bv = x; bi = k; }
    }
    #pragma unroll
    for (int o=16;o;o>>=1){
      float ov = __shfl_xor_sync(0xffffffffu, bv, o);
      int   oi = __shfl_xor_sync(0xffffffffu, bi, o);
      if (ov > bv){ bv = ov; bi = oi; }
    }
    if ((tid&31)==0){ wv[tid>>5]=bv; wi[tid>>5]=bi; }
    __syncthreads();
    if (tid==0){
      float b2 = wv[0]; int i2 = wi[0];
      #pragma unroll
      for (int w=1;w<4;w++) if (wv[w]>b2){ b2=wv[w]; i2=wi[w]; }
      tv[it]=b2; ti[it]=i2; ls[i2]=-INFINITY;
    }
    __syncthreads();
  }
  if (tid==0){
    float mx = tv[0], s = 0.f, e[KR];
    #pragma unroll
    for (int j=0;j<KR;j++){ e[j]=expf(tv[j]-mx); s+=e[j]; }
    float inv = 1.f/s;
    #pragma unroll
    for (int j=0;j<KR;j++) probs[j]=e[j]*inv;
  }
  __syncthreads();
  float pm = p_[m];
  for (int d=tid; d<DD; d+=128){
    float c = 0.f;
    #pragma unroll
    for (int j=0;j<KR;j++) c = fmaf(probs[j], S[(long)ti[j]*DD + d], c);
    out[(long)m*DD + d] = (1.f-pm)*c + pm*byp[(long)m*DD + d];
  }
}

// ---------------- host ----------------
static void* getsym(const void* sym){
  void* p = nullptr;
  cudaGetSymbolAddress(&p, sym);
  return p;
}
#define BF16P(sym) ((__nv_bfloat16*)getsym(sym))

extern "C" void kernel_launch(void* const* d_in, const int* in_sizes, int n_in,
                              void* d_out, int out_size){
  const float* x    = (const float*)d_in[0];
  const float* S    = (const float*)d_in[1];
  const float* Wq_b = (const float*)d_in[3];
  const float* Wv_b = (const float*)d_in[5];
  const float* Wn_w = (const float*)d_in[6];
  const float* Wn_b = (const float*)d_in[7];
  const float* Wm_w = (const float*)d_in[8];
  const float* Wm_b = (const float*)d_in[9];
  float* out = (float*)d_out;

  float* Q    = (float*)getsym(g_Q);
  float* V    = (float*)getsym(g_V);
  float* SC   = (float*)getsym(g_scores);
  float* BYP  = (float*)getsym(g_byp);
  float* L    = (float*)getsym(g_L);
  float* G    = (float*)getsym(g_G);
  float* RW   = (float*)getsym(g_Rw);
  float* VAG  = (float*)getsym(g_Vagg);
  float* SV   = (float*)getsym(g_SV);
  float* P2   = (float*)getsym(g_P2);
  float* R4   = (float*)getsym(g_R4);
  float* AC   = (float*)getsym(g_Acov);
  float* XA   = (float*)getsym(g_Xa);
  float* XB   = (float*)getsym(g_Xb);
  float* YT   = (float*)getsym(g_Yt);
  float* WNC0 = (float*)getsym(g_Wnc0);
  float* Wv_  = (float*)getsym(g_w);
  float* SN   = (float*)getsym(g_snorm);
  float* NOV  = (float*)getsym(g_nov);
  float* P_   = (float*)getsym(g_p);
  float* SNS  = (float*)getsym(g_SnextScratch);

  __nv_bfloat16 *xh=BF16P(g_xh), *xl=BF16P(g_xl);
  __nv_bfloat16 *Qh=BF16P(g_Qh), *Ql=BF16P(g_Ql);
  __nv_bfloat16 *Vh=BF16P(g_Vh), *Vl=BF16P(g_Vl);
  __nv_bfloat16 *Vth=BF16P(g_Vth), *Vtl=BF16P(g_Vtl);
  __nv_bfloat16 *Ph=BF16P(g_Ph), *Pl=BF16P(g_Pl);
  __nv_bfloat16 *Sh=BF16P(g_Sh), *Sl=BF16P(g_Sl);
  __nv_bfloat16 *Sth=BF16P(g_Sth), *Stl=BF16P(g_Stl);
  __nv_bfloat16 *Wqh=BF16P(g_Wqh), *Wql=BF16P(g_Wql);
  __nv_bfloat16 *Wvh=BF16P(g_Wvh), *Wvl=BF16P(g_Wvl);
  __nv_bfloat16 *WnTh=BF16P(g_WnTh), *WnTl=BF16P(g_WnTl);
  __nv_bfloat16 *RwTh=BF16P(g_RwTh), *RwTl=BF16P(g_RwTl);
  __nv_bfloat16 *P2h=BF16P(g_P2h), *P2l=BF16P(g_P2l);
  __nv_bfloat16 *ACth=BF16P(g_ACth), *ACtl=BF16P(g_ACtl);
  __nv_bfloat16 *Yh=BF16P(g_Yh), *Yl=BF16P(g_Yl);
  __nv_bfloat16 *Xah=BF16P(g_Xah), *Xal=BF16P(g_Xal);
  __nv_bfloat16 *Xath=BF16P(g_Xath), *Xatl=BF16P(g_Xatl);
  __nv_bfloat16 *Xbh=BF16P(g_Xbh), *Xbl=BF16P(g_Xbl);
  __nv_bfloat16 *Xbth=BF16P(g_Xbth), *Xbtl=BF16P(g_Xbtl);
  __nv_bfloat16 *VAGh=BF16P(g_VAGh), *VAGl=BF16P(g_VAGl);
  __nv_bfloat16 *SVh=BF16P(g_SVh), *SVl=BF16P(g_SVl);
  __nv_bfloat16 *R4h=BF16P(g_R4h), *R4l=BF16P(g_R4l);

  const long outElems = (long)BB*TT*DD + (long)BB*KK*DD;
  float* outS = (out_size >= outElems) ? out + (long)BB*TT*DD : SNS;

  const float rsqD = 0.03125f;
  const int MBT = BB*TT;
  const long ZK2 = (long)KK*KK;

  cudaFuncSetAttribute(gemm_mm, cudaFuncAttributeMaxDynamicSharedMemorySize, MM_SMEM);

  // ---- prep ordered so my launch #4 is a big gemm_mm (ncu capture slot) ----
  split_kern<<<(BB*TT*DD+255)/256, 256>>>(x, xh, xl, (long)BB*TT*DD);                 // 1
  split_kern<<<(DD*DD+255)/256, 256>>>((const float*)d_in[2], Wqh, Wql, (long)DD*DD); // 2
  split_kern<<<(DD*DD+255)/256, 256>>>((const float*)d_in[4], Wvh, Wvl, (long)DD*DD); // 3
  gemm_mm<<<dim3(DD/64, MBT/128, 1), 256, MM_SMEM>>>(                                 // 4 <- profiled
      xh, xl, DD, 0L, Wqh, Wql, DD, 0L, Q, DD, 0L, Qh, Ql, nullptr, nullptr, 0,
      DD, EPI_BIAS, 0, 0, 1.f, Wq_b, nullptr, 0L, nullptr, 0L, nullptr);
  gemm_mm<<<dim3(DD/64, MBT/128, 1), 256, MM_SMEM>>>(
      xh, xl, DD, 0L, Wvh, Wvl, DD, 0L, V, DD, 0L, Vh, Vl, nullptr, nullptr, 0,
      DD, EPI_BIAS, 0, 0, 1.f, Wv_b, nullptr, 0L, nullptr, 0L, nullptr);

  // ---- remaining prep ----
  split_kern<<<(KK*DD+255)/256, 256>>>(S, Sh, Sl, (long)KK*DD);
  tsplit_kern<<<dim3(DD/32, KK/32, 1), dim3(32,8)>>>(S, Sth, Stl, KK, DD);
  pack_wn_k<<<(KK*DD+255)/256, 256>>>(Wn_w, WnTh, WnTl, WNC0);
  prep_w_k<<<(TT+255)/256, 256>>>(Wv_);
  snorm_k<<<KK/8, 256>>>(S, SN);

  // ---- L = Q*S^T/32 ; G = V*S^T ----
  gemm_mm<<<dim3(KK/64, MBT/128, 1), 256, MM_SMEM>>>(
      Qh, Ql, DD, 0L, Sh, Sl, DD, 0L, L, KK, 0L, nullptr, nullptr, nullptr, nullptr, 0,
      DD, EPI_PLAIN, 0, 0, rsqD, nullptr, nullptr, 0L, nullptr, 0L, nullptr);
  gemm_mm<<<dim3(KK/64, MBT/128, 1), 256, MM_SMEM>>>(
      Vh, Vl, DD, 0L, Sh, Sl, DD, 0L, G, KK, 0L, nullptr, nullptr, nullptr, nullptr, 0,
      DD, EPI_PLAIN, 0, 0, 1.f, nullptr, nullptr, 0L, nullptr, 0L, nullptr);

  // ---- Vt split ----
  tsplit_kern<<<dim3(DD/32, TT/32, BB), dim3(32,8)>>>(V, Vth, Vtl, TT, DD);

  // ---- causal scores ----
  gemm_mm<<<dim3(TT/64, TT/128, BB), 256, MM_SMEM>>>(
      Qh, Ql, DD, (long)TT*DD, Qh, Ql, DD, (long)TT*DD, SC, TT, (long)TT*TT,
      nullptr, nullptr, nullptr, nullptr, 0, DD, EPI_PLAIN, 1, 0, rsqD,
      nullptr, nullptr, 0L, nullptr, 0L, nullptr);

  // ---- softmax -> split-bf16 P ----
  softmax_k<<<MBT, 256>>>(SC, Ph, Pl);

  // ---- bypass = P * Vt^T (k-limit) ----
  gemm_mm<<<dim3(DD/64, TT/128, BB), 256, MM_SMEM>>>(
      Ph, Pl, TT, (long)TT*TT, Vth, Vtl, TT, (long)DD*TT, BYP, DD, (long)TT*DD,
      nullptr, nullptr, nullptr, nullptr, 0, TT, EPI_PLAIN, 0, 1, 1.f,
      nullptr, nullptr, 0L, nullptr, 0L, nullptr);

  // ---- instr, novelty ----
  instr_k<<<MBT/8, 256>>>(Q, Wm_w, Wm_b, P_);
  novelty_k<<<MBT, 256>>>(V, G, SN, NOV);

  // ---- r_write ----
  gemm_mm<<<dim3(KK/64, MBT/128, 1), 256, MM_SMEM>>>(
      Qh, Ql, DD, 0L, WnTh, WnTl, DD, 0L, RW, KK, 0L, nullptr, nullptr, nullptr, nullptr, 0,
      DD, EPI_RW, 0, 0, 1.f, Wn_b, NOV, 0L, WNC0, 0L, Wv_);

  // ---- RwT split, V_agg (+ splits for SV) ----
  tsplit_kern<<<dim3(KK/32, TT/32, BB), dim3(32,8)>>>(RW, RwTh, RwTl, TT, KK);
  gemm_mm<<<dim3(DD/64, KK/128, BB), 256, MM_SMEM>>>(
      RwTh, RwTl, TT, (long)KK*TT, Vth, Vtl, TT, (long)DD*TT, VAG, DD, (long)KK*DD,
      VAGh, VAGl, nullptr, nullptr, 0, TT, EPI_PLAIN, 0, 0, 1.f,
      nullptr, nullptr, 0L, nullptr, 0L, nullptr);

  // ================= 512-chain, all tensor-path =================
  gemm_mm<<<dim3(KK/64, KK/128, 1), 256, MM_SMEM>>>(
      Sh, Sl, DD, 0L, Sh, Sl, DD, 0L, AC, KK, 0L,
      nullptr, nullptr, ACth, ACtl, KK, DD, EPI_COV, 0, 0, 1.f,
      nullptr, nullptr, 0L, nullptr, 0L, nullptr);

  init_x0_k<<<KK*KK/256, 256>>>(XA, Xah, Xal, Xath, Xatl, 0.64f);

  float *cur=XA, *nxt=XB;
  __nv_bfloat16 *curh=Xah, *curl=Xal, *curth=Xath, *curtl=Xatl;
  __nv_bfloat16 *nxth=Xbh, *nxtl=Xbl, *nxtth=Xbth, *nxttl=Xbtl;
  for (int it=0; it<8; it++){
    gemm_mm<<<dim3(KK/64, KK/128, 1), 256, MM_SMEM>>>(
        curh, curl, KK, 0L, ACth, ACtl, KK, 0L, YT, KK, 0L,
        Yh, Yl, nullptr, nullptr, 0, KK, EPI_PLAIN, 0, 0, 1.f,
        nullptr, nullptr, 0L, nullptr, 0L, nullptr);
    gemm_mm<<<dim3(KK/64, KK/128, 1), 256, MM_SMEM>>>(
        Yh, Yl, KK, 0L, curth, curtl, KK, 0L, nxt, KK, 0L,
        nxth, nxtl, nxtth, nxttl, KK, KK, EPI_NS, 0, 0, 1.f,
        nullptr, cur, 0L, nullptr, 0L, nullptr);
    float* tf=cur; cur=nxt; nxt=tf;
    __nv_bfloat16* tb;
    tb=curh; curh=nxth; nxth=tb;   tb=curl; curl=nxtl; nxtl=tb;
    tb=curth; curth=nxtth; nxtth=tb; tb=curtl; curtl=nxttl; nxttl=tb;
  }

  gemm_mm<<<dim3(KK/64, KK/128, BB), 256, MM_SMEM>>>(
      VAGh, VAGl, DD, (long)KK*DD, Sh, Sl, DD, 0L, SV, KK, ZK2,
      SVh, SVl, nullptr, nullptr, 0, DD, EPI_PLAIN, 0, 0, 1.f,
      nullptr, nullptr, 0L, nullptr, 0L, nullptr);
  gemm_mm<<<dim3(KK/64, KK/128, BB), 256, MM_SMEM>>>(
      SVh, SVl, KK, ZK2, curth, curtl, KK, 0L, P2, KK, ZK2,
      P2h, P2l, nullptr, nullptr, 0, KK, EPI_PLAIN, 0, 0, 1.f,
      nullptr, nullptr, 0L, nullptr, 0L, nullptr);
  gemm_mm<<<dim3(KK/64, KK/128, BB), 256, MM_SMEM>>>(
      P2h, P2l, KK, ZK2, ACth, ACtl, KK, 0L, R4, KK, ZK2,
      R4h, R4l, nullptr, nullptr, 0, KK, EPI_RSUB, 0, 0, 1.f,
      nullptr, SV, ZK2, nullptr, 0L, nullptr);
  gemm_mm<<<dim3(KK/64, KK/128, BB), 256, MM_SMEM>>>(
      R4h, R4l, KK, ZK2, curth, curtl, KK, 0L, P2, KK, ZK2,
      P2h, P2l, nullptr, nullptr, 0, KK, EPI_ADD, 0, 0, 1.f,
      nullptr, P2, ZK2, nullptr, 0L, nullptr);

  gemm_mm<<<dim3(DD/64, KK/128, BB), 256, MM_SMEM>>>(
      P2h, P2l, KK, ZK2, Sth, Stl, KK, 0L, outS, DD, (long)KK*DD,
      nullptr, nullptr, nullptr, nullptr, 0, KK, EPI_SNEXT, 0, 0, 1.f,
      nullptr, S, 0L, VAG, (long)KK*DD, nullptr);

  // ---- topk + combine -> out ----
  topk_k<<<MBT, 128>>>(L, S, P_, BYP, out);
}

// round 16
// speedup vs baseline: 1.1201x; 1.1201x over previous
#include <cuda_runtime.h>
#include <cuda_bf16.h>
#include <cstdint>
#include <math.h>

typedef unsigned int u32;
typedef unsigned long long u64;

// ---------------- problem constants ----------------
#define BB 4
#define TT 2048
#define DD 1024
#define KK 512
#define KR 16

// ---------------- fp32 scratch ----------------
__device__ float g_Q[BB*TT*DD];
__device__ float g_V[BB*TT*DD];
__device__ float g_scores[(long)BB*TT*TT];
__device__ float g_byp[BB*TT*DD];
__device__ float g_L[BB*TT*KK];
__device__ float g_G[BB*TT*KK];
__device__ float g_Rw[BB*TT*KK];
__device__ float g_Vagg[BB*KK*DD];
__device__ float g_SV[BB*KK*KK];
__device__ float g_P2[BB*KK*KK];
__device__ float g_R4[BB*KK*KK];
__device__ float g_Acov[KK*KK];
__device__ float g_Xa[KK*KK];
__device__ float g_Xb[KK*KK];
__device__ float g_Yt[KK*KK];
__device__ float g_Wnc0[KK];
__device__ float g_w[TT];
__device__ float g_snorm[KK];
__device__ float g_nov[BB*TT];
__device__ float g_p[BB*TT];
__device__ float g_SnextScratch[BB*KK*DD];

// ---------------- bf16 split scratch ----------------
__device__ __nv_bfloat16 g_xh[BB*TT*DD];
__device__ __nv_bfloat16 g_xl[BB*TT*DD];
__device__ __nv_bfloat16 g_Qh[BB*TT*DD];
__device__ __nv_bfloat16 g_Ql[BB*TT*DD];
__device__ __nv_bfloat16 g_Vh[BB*TT*DD];
__device__ __nv_bfloat16 g_Vl[BB*TT*DD];
__device__ __nv_bfloat16 g_Vth[BB*DD*TT];
__device__ __nv_bfloat16 g_Vtl[BB*DD*TT];
__device__ __nv_bfloat16 g_Ph[(long)BB*TT*TT];
__device__ __nv_bfloat16 g_Pl[(long)BB*TT*TT];
__device__ __nv_bfloat16 g_Sh[KK*DD];
__device__ __nv_bfloat16 g_Sl[KK*DD];
__device__ __nv_bfloat16 g_Sth[DD*KK];
__device__ __nv_bfloat16 g_Stl[DD*KK];
__device__ __nv_bfloat16 g_Wqh[DD*DD];
__device__ __nv_bfloat16 g_Wql[DD*DD];
__device__ __nv_bfloat16 g_Wvh[DD*DD];
__device__ __nv_bfloat16 g_Wvl[DD*DD];
__device__ __nv_bfloat16 g_WnTh[KK*DD];
__device__ __nv_bfloat16 g_WnTl[KK*DD];
__device__ __nv_bfloat16 g_RwTh[BB*KK*TT];
__device__ __nv_bfloat16 g_RwTl[BB*KK*TT];
__device__ __nv_bfloat16 g_P2h[BB*KK*KK];
__device__ __nv_bfloat16 g_P2l[BB*KK*KK];
// chain operand forms
__device__ __nv_bfloat16 g_ACth[KK*KK];
__device__ __nv_bfloat16 g_ACtl[KK*KK];
__device__ __nv_bfloat16 g_Yh[KK*KK];
__device__ __nv_bfloat16 g_Yl[KK*KK];
__device__ __nv_bfloat16 g_Xah[KK*KK];
__device__ __nv_bfloat16 g_Xal[KK*KK];
__device__ __nv_bfloat16 g_Xath[KK*KK];
__device__ __nv_bfloat16 g_Xatl[KK*KK];
__device__ __nv_bfloat16 g_Xbh[KK*KK];
__device__ __nv_bfloat16 g_Xbl[KK*KK];
__device__ __nv_bfloat16 g_Xbth[KK*KK];
__device__ __nv_bfloat16 g_Xbtl[KK*KK];
__device__ __nv_bfloat16 g_VAGh[BB*KK*DD];
__device__ __nv_bfloat16 g_VAGl[BB*KK*DD];
__device__ __nv_bfloat16 g_SVh[BB*KK*KK];
__device__ __nv_bfloat16 g_SVl[BB*KK*KK];
__device__ __nv_bfloat16 g_R4h[BB*KK*KK];
__device__ __nv_bfloat16 g_R4l[BB*KK*KK];

// ---------------- reductions ----------------
__device__ __forceinline__ float warpReduceSum(float v){
  #pragma unroll
  for (int o=16;o;o>>=1) v += __shfl_xor_sync(0xffffffffu, v, o);
  return v;
}
__device__ __forceinline__ float warpReduceMax(float v){
  #pragma unroll
  for (int o=16;o;o>>=1) v = fmaxf(v, __shfl_xor_sync(0xffffffffu, v, o));
  return v;
}
__device__ float blockReduceSum(float v){
  __shared__ float sh[33];
  int lane = threadIdx.x & 31, wid = threadIdx.x >> 5, nw = blockDim.x >> 5;
  v = warpReduceSum(v);
  __syncthreads();
  if (lane==0) sh[wid]=v;
  __syncthreads();
  if (wid==0){
    float r = (lane<nw)? sh[lane] : 0.f;
    r = warpReduceSum(r);
    if (lane==0) sh[32]=r;
  }
  __syncthreads();
  return sh[32];
}
__device__ float blockReduceMax(float v){
  __shared__ float sh[33];
  int lane = threadIdx.x & 31, wid = threadIdx.x >> 5, nw = blockDim.x >> 5;
  v = warpReduceMax(v);
  __syncthreads();
  if (lane==0) sh[wid]=v;
  __syncthreads();
  if (wid==0){
    float r = (lane<nw)? sh[lane] : -INFINITY;
    r = warpReduceMax(r);
    if (lane==0) sh[32]=r;
  }
  __syncthreads();
  return sh[32];
}

// ================= mma.sync helpers =================
__device__ __forceinline__ void ldsm4(u32& r0, u32& r1, u32& r2, u32& r3, u32 saddr){
  asm volatile("ldmatrix.sync.aligned.m8n8.x4.shared.b16 {%0,%1,%2,%3}, [%4];"
    : "=r"(r0), "=r"(r1), "=r"(r2), "=r"(r3) : "r"(saddr));
}
__device__ __forceinline__ void mma16816(float* c, const u32* a, const u32* b){
  asm volatile(
    "mma.sync.aligned.m16n8k16.row.col.f32.bf16.bf16.f32 "
    "{%0,%1,%2,%3}, {%4,%5,%6,%7}, {%8,%9}, {%0,%1,%2,%3};"
    : "+f"(c[0]), "+f"(c[1]), "+f"(c[2]), "+f"(c[3])
    : "r"(a[0]), "r"(a[1]), "r"(a[2]), "r"(a[3]), "r"(b[0]), "r"(b[1]));
}
__device__ __forceinline__ void cpasync16(u32 dst, const void* src){
  asm volatile("cp.async.cg.shared.global [%0], [%1], 16;" :: "r"(dst), "l"(src));
}

// epilogue codes
#define EPI_PLAIN 0
#define EPI_BIAS  1
#define EPI_COV   2
#define EPI_RW    3
#define EPI_NS    4
#define EPI_SNEXT 5
#define EPI_RSUB  6
#define EPI_ADD   7

#define ROWB 144
#define ARR_B (128*ROWB)
#define ST_B  (4*ARR_B)
#define MM_SMEM (2*ST_B)

// ================= bf16 split NT GEMM via mma.sync: C = A*B^T =================
// 512 thr (4x4 warps), 128x128 tile, BK=64, 2-stage cp.async pipeline,
// frag double-buffer + term-major MMA. nterms: 3 = hi*hi+hi*lo+lo*hi (full
// split, ~1e-5 rel err), 1 = hi*hi only (~4e-3 rel err; for noise-tolerant
// consumers: novelty sims, Newton-Schulz iterates fixed by refinement).
__global__ void __launch_bounds__(512)
gemm_mm(const __nv_bfloat16* Ah, const __nv_bfloat16* Al, int lda, long sA,
        const __nv_bfloat16* Bh, const __nv_bfloat16* Bl, int ldb, long sB,
        float* C, int ldc, long sC,
        __nv_bfloat16* Coh, __nv_bfloat16* Col,
        __nv_bfloat16* Cth, __nv_bfloat16* Ctl, int ldt,
        int Kd, int nterms, int epi, int cskip, int klim, float alpha,
        const float* bias, const float* aux1, long s1,
        const float* aux2, long s2, const float* rowv)
{
  if (cskip && (int)blockIdx.x > (int)blockIdx.y) return;
  extern __shared__ __nv_bfloat16 dynsm[];

  const int tid  = threadIdx.x;
  const int lane = tid & 31;
  const int warp = tid >> 5;
  const int wm = warp >> 2, wn = warp & 3;
  const int m0 = blockIdx.y*128, n0 = blockIdx.x*128;
  const long z = blockIdx.z;
  Ah += z*sA; Al += z*sA; Bh += z*sB; Bl += z*sB; C += z*sC;
  const float* ax1 = aux1 ? aux1 + z*s1 : aux1;
  const float* ax2 = aux2 ? aux2 + z*s2 : aux2;

  const u32 sm0 = (u32)__cvta_generic_to_shared(dynsm);

  float acc[2][4][4];
  #pragma unroll
  for (int i=0;i<2;i++)
    #pragma unroll
    for (int j=0;j<4;j++)
      #pragma unroll
      for (int q=0;q<4;q++) acc[i][j][q] = 0.f;

  const int kend = klim ? min(Kd, m0+128) : Kd;
  const int nch  = kend >> 6;
  const bool full = (nterms == 3);

  const int lr = tid >> 2;
  const int lq = (tid & 3) * 16;
  const __nv_bfloat16* gA_h = Ah + (long)(m0+lr)*lda + lq;
  const __nv_bfloat16* gA_l = Al + (long)(m0+lr)*lda + lq;
  const __nv_bfloat16* gB_h = Bh + (long)(n0+lr)*ldb + lq;
  const __nv_bfloat16* gB_l = Bl + (long)(n0+lr)*ldb + lq;
  const u32 dst0 = sm0 + lr*ROWB + lq*2;

  auto issue_chunk = [&](int cc, int ss){
    int k0 = cc << 6;
    u32 dst = dst0 + ss*ST_B;
    cpasync16(dst,                gA_h + k0);
    cpasync16(dst + 16,           gA_h + k0 + 8);
    cpasync16(dst + 2*ARR_B,      gB_h + k0);
    cpasync16(dst + 2*ARR_B + 16, gB_h + k0 + 8);
    if (full){
      cpasync16(dst +   ARR_B,      gA_l + k0);
      cpasync16(dst +   ARR_B + 16, gA_l + k0 + 8);
      cpasync16(dst + 3*ARR_B,      gB_l + k0);
      cpasync16(dst + 3*ARR_B + 16, gB_l + k0 + 8);
    }
    asm volatile("cp.async.commit_group;" ::: "memory");
  };

  issue_chunk(0, 0);

  u32 fa_h[2][2][4], fa_l[2][2][4];
  u32 fb_h[2][4][2], fb_l[2][4][2];

  const int ga  = lane >> 3;
  const int ar_ = (ga & 1)*8 + (lane & 7);
  const int br_ = (ga >> 1)*8 + (lane & 7);

  for (int c=0; c<nch; c++){
    asm volatile("cp.async.wait_group 0;" ::: "memory");
    __syncthreads();
    if (c+1 < nch) issue_chunk(c+1, (c+1)&1);

    const u32 sbase = sm0 + (c&1)*ST_B;

    {
      int ac = (ga >> 1)*8;
      #pragma unroll
      for (int mt=0; mt<2; mt++){
        u32 sa = sbase + (wm*32 + mt*16 + ar_)*ROWB + ac*2;
        ldsm4(fa_h[0][mt][0], fa_h[0][mt][1], fa_h[0][mt][2], fa_h[0][mt][3], sa);
        if (full)
          ldsm4(fa_l[0][mt][0], fa_l[0][mt][1], fa_l[0][mt][2], fa_l[0][mt][3], sa + ARR_B);
      }
      int bc = (ga & 1)*8;
      #pragma unroll
      for (int pr=0; pr<2; pr++){
        u32 sb = sbase + 2*ARR_B + (wn*32 + pr*16 + br_)*ROWB + bc*2;
        ldsm4(fb_h[0][pr*2][0], fb_h[0][pr*2][1], fb_h[0][pr*2+1][0], fb_h[0][pr*2+1][1], sb);
        if (full)
          ldsm4(fb_l[0][pr*2][0], fb_l[0][pr*2][1], fb_l[0][pr*2+1][0], fb_l[0][pr*2+1][1], sb + ARR_B);
      }
    }

    #pragma unroll
    for (int i=0; i<4; i++){
      const int cb = i & 1, nb = cb ^ 1;
      if (i < 3){
        int kk = (i+1) << 4;
        int ac = kk + (ga >> 1)*8;
        #pragma unroll
        for (int mt=0; mt<2; mt++){
          u32 sa = sbase + (wm*32 + mt*16 + ar_)*ROWB + ac*2;
          ldsm4(fa_h[nb][mt][0], fa_h[nb][mt][1], fa_h[nb][mt][2], fa_h[nb][mt][3], sa);
          if (full)
            ldsm4(fa_l[nb][mt][0], fa_l[nb][mt][1], fa_l[nb][mt][2], fa_l[nb][mt][3], sa + ARR_B);
        }
        int bc = kk + (ga & 1)*8;
        #pragma unroll
        for (int pr=0; pr<2; pr++){
          u32 sb = sbase + 2*ARR_B + (wn*32 + pr*16 + br_)*ROWB + bc*2;
          ldsm4(fb_h[nb][pr*2][0], fb_h[nb][pr*2][1], fb_h[nb][pr*2+1][0], fb_h[nb][pr*2+1][1], sb);
          if (full)
            ldsm4(fb_l[nb][pr*2][0], fb_l[nb][pr*2][1], fb_l[nb][pr*2+1][0], fb_l[nb][pr*2+1][1], sb + ARR_B);
        }
      }
      #pragma unroll
      for (int mt=0; mt<2; mt++)
        #pragma unroll
        for (int nt=0; nt<4; nt++)
          mma16816(acc[mt][nt], fa_h[cb][mt], fb_h[cb][nt]);
      if (full){
        #pragma unroll
        for (int mt=0; mt<2; mt++)
          #pragma unroll
          for (int nt=0; nt<4; nt++)
            mma16816(acc[mt][nt], fa_h[cb][mt], fb_l[cb][nt]);
        #pragma unroll
        for (int mt=0; mt<2; mt++)
          #pragma unroll
          for (int nt=0; nt<4; nt++)
            mma16816(acc[mt][nt], fa_l[cb][mt], fb_h[cb][nt]);
      }
    }
  }

  // ---- epilogue ----
  const int gr = lane >> 2;
  const int tc = (lane & 3) * 2;
  #pragma unroll
  for (int mt=0; mt<2; mt++){
    #pragma unroll
    for (int h=0; h<2; h++){
      int r = m0 + wm*32 + mt*16 + h*8 + gr;
      float* Crow = C + (long)r*ldc;
      #pragma unroll
      for (int nt=0; nt<4; nt++){
        int ccol = n0 + wn*32 + nt*8 + tc;
        float v0 = acc[mt][nt][h*2], v1 = acc[mt][nt][h*2+1];
        if (epi == EPI_PLAIN){
          v0 *= alpha; v1 *= alpha;
        } else if (epi == EPI_BIAS){
          v0 += bias[ccol]; v1 += bias[ccol+1];
        } else if (epi == EPI_RW){
          float a1r = ax1[r], rv = rowv[r & (TT-1)];
          float x0 = v0 + a1r*ax2[ccol]   + bias[ccol];
          float x1 = v1 + a1r*ax2[ccol+1] + bias[ccol+1];
          v0 = rv / (1.f + expf(-x0));
          v1 = rv / (1.f + expf(-x1));
        } else if (epi == EPI_SNEXT){
          v0 = 0.99f*ax1[(long)r*ldc + ccol]   + 0.1f*(ax2[(long)r*ldc + ccol]   - v0);
          v1 = 0.99f*ax1[(long)r*ldc + ccol+1] + 0.1f*(ax2[(long)r*ldc + ccol+1] - v1);
        } else if (epi == EPI_COV){
          if (r == ccol)   v0 += 1e-5f;
          if (r == ccol+1) v1 += 1e-5f;
        } else if (epi == EPI_NS){
          v0 = 2.f*ax1[(long)r*ldc + ccol]   - v0;
          v1 = 2.f*ax1[(long)r*ldc + ccol+1] - v1;
        } else if (epi == EPI_RSUB){
          v0 = ax1[(long)r*ldc + ccol]   - v0;
          v1 = ax1[(long)r*ldc + ccol+1] - v1;
        } else if (epi == EPI_ADD){
          v0 = ax1[(long)r*ldc + ccol]   + v0;
          v1 = ax1[(long)r*ldc + ccol+1] + v1;
        }
        *(float2*)(Crow + ccol) = make_float2(v0, v1);
        __nv_bfloat16 h0, h1, l0, l1;
        if (Coh || Cth){
          h0 = __float2bfloat16(v0);
          h1 = __float2bfloat16(v1);
          l0 = __float2bfloat16(v0 - __bfloat162float(h0));
          l1 = __float2bfloat16(v1 - __bfloat162float(h1));
        }
        if (Coh){
          *(__nv_bfloat162*)(Coh + z*sC + (long)r*ldc + ccol) = __halves2bfloat162(h0, h1);
          *(__nv_bfloat162*)(Col + z*sC + (long)r*ldc + ccol) = __halves2bfloat162(l0, l1);
        }
        if (Cth){
          Cth[z*sC + (long)ccol*ldt + r]     = h0;
          Ctl[z*sC + (long)ccol*ldt + r]     = l0;
          Cth[z*sC + (long)(ccol+1)*ldt + r] = h1;
          Ctl[z*sC + (long)(ccol+1)*ldt + r] = l1;
        }
      }
    }
  }
}

// ---------------- elementwise / prep kernels ----------------
__global__ void split_kern(const float* __restrict__ X, __nv_bfloat16* __restrict__ H,
                           __nv_bfloat16* __restrict__ Lo, long n){
  long i = (long)blockIdx.x*256 + threadIdx.x;
  if (i < n){
    float v = X[i];
    __nv_bfloat16 h = __float2bfloat16(v);
    H[i] = h;
    Lo[i] = __float2bfloat16(v - __bfloat162float(h));
  }
}

__global__ void tsplit_kern(const float* __restrict__ X, __nv_bfloat16* __restrict__ TH,
                            __nv_bfloat16* __restrict__ TL, int R, int Cc){
  __shared__ float tile[32][33];
  const float* Xz = X + (long)blockIdx.z*R*Cc;
  __nv_bfloat16* THz = TH + (long)blockIdx.z*R*Cc;
  __nv_bfloat16* TLz = TL + (long)blockIdx.z*R*Cc;
  int c0 = blockIdx.x*32, r0 = blockIdx.y*32;
  int tx = threadIdx.x, ty = threadIdx.y;
  for (int i=ty; i<32; i+=8)
    tile[i][tx] = Xz[(long)(r0+i)*Cc + c0 + tx];
  __syncthreads();
  for (int i=ty; i<32; i+=8){
    float v = tile[tx][i];
    __nv_bfloat16 h = __float2bfloat16(v);
    long o = (long)(c0+i)*R + r0 + tx;
    THz[o] = h;
    TLz[o] = __float2bfloat16(v - __bfloat162float(h));
  }
}

__global__ void pack_wn_k(const float* __restrict__ Wn, __nv_bfloat16* __restrict__ H,
                          __nv_bfloat16* __restrict__ Lo, float* __restrict__ c0){
  long i = (long)blockIdx.x*256 + threadIdx.x;
  if (i < (long)KK*DD){
    int k = (int)(i >> 10), d = (int)(i & 1023);
    float v = Wn[(long)k*(DD+1) + 1 + d];
    __nv_bfloat16 h = __float2bfloat16(v);
    H[i] = h;
    Lo[i] = __float2bfloat16(v - __bfloat162float(h));
    if (d==0) c0[k] = Wn[(long)k*(DD+1)];
  }
}

__global__ void prep_w_k(float* __restrict__ w){
  int t = blockIdx.x*256 + threadIdx.x;
  if (t < TT){
    double z = (1.0 - pow(0.99, (double)TT)) / 0.01;
    w[t] = (float)(pow(0.99, (double)(TT-1-t)) / z);
  }
}

__global__ void snorm_k(const float* __restrict__ S, float* __restrict__ sn){
  int k = blockIdx.x*8 + (threadIdx.x>>5);
  int lane = threadIdx.x & 31;
  float s = 0.f;
  const float4* row = (const float4*)(S + (long)k*DD);
  for (int i=lane; i<DD/4; i+=32){ float4 a = row[i]; s += a.x*a.x+a.y*a.y+a.z*a.z+a.w*a.w; }
  s = warpReduceSum(s);
  if (lane==0) sn[k] = fmaxf(sqrtf(s), 1e-8f);
}

__global__ void init_x0_k(float* __restrict__ X,
                          __nv_bfloat16* __restrict__ Xh, __nv_bfloat16* __restrict__ Xl,
                          __nv_bfloat16* __restrict__ Xth, __nv_bfloat16* __restrict__ Xtl,
                          float alpha){
  int i = blockIdx.x*256 + threadIdx.x;
  int r = i >> 9, c = i & (KK-1);
  float v = (r==c) ? alpha : 0.f;
  X[i] = v;
  __nv_bfloat16 h = __float2bfloat16(v);
  __nv_bfloat16 l = __float2bfloat16(v - __bfloat162float(h));
  Xh[i] = h; Xl[i] = l;
  long t = (long)c*KK + r;
  Xth[t] = h; Xtl[t] = l;
}

__global__ void instr_k(const float* __restrict__ Q, const float* __restrict__ Wm,
                        const float* __restrict__ Wmb, float* __restrict__ p){
  int m = blockIdx.x*8 + (threadIdx.x>>5);
  int lane = threadIdx.x & 31;
  const float4* q = (const float4*)(Q + (long)m*DD);
  const float4* w = (const float4*)Wm;
  float acc = 0.f;
  for (int i=lane; i<DD/4; i+=32){
    float4 a=q[i], b=w[i];
    acc += a.x*b.x + a.y*b.y + a.z*b.z + a.w*b.w;
  }
  acc = warpReduceSum(acc);
  if (lane==0){
    p[m] = 1.f/(1.f+expf(-(acc + Wmb[0])));
  }
}

__global__ void novelty_k(const float* __restrict__ V, const float* __restrict__ G,
                          const float* __restrict__ sn, float* __restrict__ nov){
  int m = blockIdx.x;
  float s = 0.f;
  for (int d=threadIdx.x; d<DD; d+=256){ float x = V[(long)m*DD+d]; s += x*x; }
  s = blockReduceSum(s);
  float vn = fmaxf(sqrtf(s), 1e-8f);
  float mx = -INFINITY;
  for (int k=threadIdx.x; k<KK; k+=256) mx = fmaxf(mx, G[(long)m*KK+k] / (vn*sn[k]));
  mx = blockReduceMax(mx);
  if (threadIdx.x==0) nov[m] = 1.f - mx;
}

__global__ void softmax_k(const float* __restrict__ sc,
                          __nv_bfloat16* __restrict__ Ph, __nv_bfloat16* __restrict__ Pl){
  int m = blockIdx.x;
  int q = m & (TT-1);
  const float* row = sc + (long)m*TT;
  __nv_bfloat16* ph = Ph + (long)m*TT;
  __nv_bfloat16* pl = Pl + (long)m*TT;
  int len = q+1;
  int kend = ((q>>7)+1) << 7;
  float mx = -INFINITY;
  for (int k=threadIdx.x; k<len; k+=256) mx = fmaxf(mx, row[k]);
  mx = blockReduceMax(mx);
  float s = 0.f;
  for (int k=threadIdx.x; k<len; k+=256) s += expf(row[k]-mx);
  s = blockReduceSum(s);
  float inv = 1.f/s;
  for (int k=threadIdx.x; k<kend; k+=256){
    float p = (k<len) ? expf(row[k]-mx)*inv : 0.f;
    __nv_bfloat16 h = __float2bfloat16(p);
    ph[k] = h;
    pl[k] = __float2bfloat16(p - __bfloat162float(h));
  }
}

__global__ void __launch_bounds__(128)
topk_k(const float* __restrict__ L, const float* __restrict__ S,
       const float* __restrict__ p_, const float* __restrict__ byp,
       float* __restrict__ out){
  __shared__ float ls[KK];
  __shared__ float tv[KR];
  __shared__ int   ti[KR];
  __shared__ float wv[4];
  __shared__ int   wi[4];
  __shared__ float probs[KR];
  int m = blockIdx.x, tid = threadIdx.x;
  for (int k=tid; k<KK; k+=128) ls[k] = L[(long)m*KK + k];
  __syncthreads();
  for (int it=0; it<KR; it++){
    float bv = -INFINITY; int bi = 0;
    #pragma unroll
    for (int u=0; u<KK/128; u++){
      int k = tid + u*128;
      float x = ls[k];
      if (x > bv){ bv = x; bi = k; }
    }
    #pragma unroll
    for (int o=16;o;o>>=1){
      float ov = __shfl_xor_sync(0xffffffffu, bv, o);
      int   oi = __shfl_xor_sync(0xffffffffu, bi, o);
      if (ov > bv){ bv = ov; bi = oi; }
    }
    if ((tid&31)==0){ wv[tid>>5]=bv; wi[tid>>5]=bi; }
    __syncthreads();
    if (tid==0){
      float b2 = wv[0]; int i2 = wi[0];
      #pragma unroll
      for (int w=1;w<4;w++) if (wv[w]>b2){ b2=wv[w]; i2=wi[w]; }
      tv[it]=b2; ti[it]=i2; ls[i2]=-INFINITY;
    }
    __syncthreads();
  }
  if (tid==0){
    float mx = tv[0], s = 0.f, e[KR];
    #pragma unroll
    for (int j=0;j<KR;j++){ e[j]=expf(tv[j]-mx); s+=e[j]; }
    float inv = 1.f/s;
    #pragma unroll
    for (int j=0;j<KR;j++) probs[j]=e[j]*inv;
  }
  __syncthreads();
  float pm = p_[m];
  for (int d=tid; d<DD; d+=128){
    float c = 0.f;
    #pragma unroll
    for (int j=0;j<KR;j++) c = fmaf(probs[j], S[(long)ti[j]*DD + d], c);
    out[(long)m*DD + d] = (1.f-pm)*c + pm*byp[(long)m*DD + d];
  }
}

// ---------------- host ----------------
static void* getsym(const void* sym){
  void* p = nullptr;
  cudaGetSymbolAddress(&p, sym);
  return p;
}
#define BF16P(sym) ((__nv_bfloat16*)getsym(sym))

extern "C" void kernel_launch(void* const* d_in, const int* in_sizes, int n_in,
                              void* d_out, int out_size){
  const float* x    = (const float*)d_in[0];
  const float* S    = (const float*)d_in[1];
  const float* Wq_b = (const float*)d_in[3];
  const float* Wv_b = (const float*)d_in[5];
  const float* Wn_w = (const float*)d_in[6];
  const float* Wn_b = (const float*)d_in[7];
  const float* Wm_w = (const float*)d_in[8];
  const float* Wm_b = (const float*)d_in[9];
  float* out = (float*)d_out;

  float* Q    = (float*)getsym(g_Q);
  float* V    = (float*)getsym(g_V);
  float* SC   = (float*)getsym(g_scores);
  float* BYP  = (float*)getsym(g_byp);
  float* L    = (float*)getsym(g_L);
  float* G    = (float*)getsym(g_G);
  float* RW   = (float*)getsym(g_Rw);
  float* VAG  = (float*)getsym(g_Vagg);
  float* SV   = (float*)getsym(g_SV);
  float* P2   = (float*)getsym(g_P2);
  float* R4   = (float*)getsym(g_R4);
  float* AC   = (float*)getsym(g_Acov);
  float* XA   = (float*)getsym(g_Xa);
  float* XB   = (float*)getsym(g_Xb);
  float* YT   = (float*)getsym(g_Yt);
  float* WNC0 = (float*)getsym(g_Wnc0);
  float* Wv_  = (float*)getsym(g_w);
  float* SN   = (float*)getsym(g_snorm);
  float* NOV  = (float*)getsym(g_nov);
  float* P_   = (float*)getsym(g_p);
  float* SNS  = (float*)getsym(g_SnextScratch);

  __nv_bfloat16 *xh=BF16P(g_xh), *xl=BF16P(g_xl);
  __nv_bfloat16 *Qh=BF16P(g_Qh), *Ql=BF16P(g_Ql);
  __nv_bfloat16 *Vh=BF16P(g_Vh), *Vl=BF16P(g_Vl);
  __nv_bfloat16 *Vth=BF16P(g_Vth), *Vtl=BF16P(g_Vtl);
  __nv_bfloat16 *Ph=BF16P(g_Ph), *Pl=BF16P(g_Pl);
  __nv_bfloat16 *Sh=BF16P(g_Sh), *Sl=BF16P(g_Sl);
  __nv_bfloat16 *Sth=BF16P(g_Sth), *Stl=BF16P(g_Stl);
  __nv_bfloat16 *Wqh=BF16P(g_Wqh), *Wql=BF16P(g_Wql);
  __nv_bfloat16 *Wvh=BF16P(g_Wvh), *Wvl=BF16P(g_Wvl);
  __nv_bfloat16 *WnTh=BF16P(g_WnTh), *WnTl=BF16P(g_WnTl);
  __nv_bfloat16 *RwTh=BF16P(g_RwTh), *RwTl=BF16P(g_RwTl);
  __nv_bfloat16 *P2h=BF16P(g_P2h), *P2l=BF16P(g_P2l);
  __nv_bfloat16 *ACth=BF16P(g_ACth), *ACtl=BF16P(g_ACtl);
  __nv_bfloat16 *Yh=BF16P(g_Yh), *Yl=BF16P(g_Yl);
  __nv_bfloat16 *Xah=BF16P(g_Xah), *Xal=BF16P(g_Xal);
  __nv_bfloat16 *Xath=BF16P(g_Xath), *Xatl=BF16P(g_Xatl);
  __nv_bfloat16 *Xbh=BF16P(g_Xbh), *Xbl=BF16P(g_Xbl);
  __nv_bfloat16 *Xbth=BF16P(g_Xbth), *Xbtl=BF16P(g_Xbtl);
  __nv_bfloat16 *VAGh=BF16P(g_VAGh), *VAGl=BF16P(g_VAGl);
  __nv_bfloat16 *SVh=BF16P(g_SVh), *SVl=BF16P(g_SVl);
  __nv_bfloat16 *R4h=BF16P(g_R4h), *R4l=BF16P(g_R4l);

  const long outElems = (long)BB*TT*DD + (long)BB*KK*DD;
  float* outS = (out_size >= outElems) ? out + (long)BB*TT*DD : SNS;

  const float rsqD = 0.03125f;
  const int MBT = BB*TT;
  const long ZK2 = (long)KK*KK;

  cudaFuncSetAttribute(gemm_mm, cudaFuncAttributeMaxDynamicSharedMemorySize, MM_SMEM);

  // ---- prep ordered so my launch #4 is a big gemm_mm (ncu capture slot) ----
  split_kern<<<(BB*TT*DD+255)/256, 256>>>(x, xh, xl, (long)BB*TT*DD);
  split_kern<<<(DD*DD+255)/256, 256>>>((const float*)d_in[2], Wqh, Wql, (long)DD*DD);
  split_kern<<<(DD*DD+255)/256, 256>>>((const float*)d_in[4], Wvh, Wvl, (long)DD*DD);
  gemm_mm<<<dim3(DD/128, MBT/128, 1), 512, MM_SMEM>>>(
      xh, xl, DD, 0L, Wqh, Wql, DD, 0L, Q, DD, 0L, Qh, Ql, nullptr, nullptr, 0,
      DD, 3, EPI_BIAS, 0, 0, 1.f, Wq_b, nullptr, 0L, nullptr, 0L, nullptr);
  gemm_mm<<<dim3(DD/128, MBT/128, 1), 512, MM_SMEM>>>(
      xh, xl, DD, 0L, Wvh, Wvl, DD, 0L, V, DD, 0L, Vh, Vl, nullptr, nullptr, 0,
      DD, 3, EPI_BIAS, 0, 0, 1.f, Wv_b, nullptr, 0L, nullptr, 0L, nullptr);

  // ---- remaining prep ----
  split_kern<<<(KK*DD+255)/256, 256>>>(S, Sh, Sl, (long)KK*DD);
  tsplit_kern<<<dim3(DD/32, KK/32, 1), dim3(32,8)>>>(S, Sth, Stl, KK, DD);
  pack_wn_k<<<(KK*DD+255)/256, 256>>>(Wn_w, WnTh, WnTl, WNC0);
  prep_w_k<<<(TT+255)/256, 256>>>(Wv_);
  snorm_k<<<KK/8, 256>>>(S, SN);

  // ---- L = Q*S^T/32 (3-term) ; G = V*S^T (1-term: feeds only novelty max) ----
  gemm_mm<<<dim3(KK/128, MBT/128, 1), 512, MM_SMEM>>>(
      Qh, Ql, DD, 0L, Sh, Sl, DD, 0L, L, KK, 0L, nullptr, nullptr, nullptr, nullptr, 0,
      DD, 3, EPI_PLAIN, 0, 0, rsqD, nullptr, nullptr, 0L, nullptr, 0L, nullptr);
  gemm_mm<<<dim3(KK/128, MBT/128, 1), 512, MM_SMEM>>>(
      Vh, Vl, DD, 0L, Sh, Sl, DD, 0L, G, KK, 0L, nullptr, nullptr, nullptr, nullptr, 0,
      DD, 1, EPI_PLAIN, 0, 0, 1.f, nullptr, nullptr, 0L, nullptr, 0L, nullptr);

  // ---- Vt split ----
  tsplit_kern<<<dim3(DD/32, TT/32, BB), dim3(32,8)>>>(V, Vth, Vtl, TT, DD);

  // ---- causal scores ----
  gemm_mm<<<dim3(TT/128, TT/128, BB), 512, MM_SMEM>>>(
      Qh, Ql, DD, (long)TT*DD, Qh, Ql, DD, (long)TT*DD, SC, TT, (long)TT*TT,
      nullptr, nullptr, nullptr, nullptr, 0, DD, 3, EPI_PLAIN, 1, 0, rsqD,
      nullptr, nullptr, 0L, nullptr, 0L, nullptr);

  // ---- softmax -> split-bf16 P ----
  softmax_k<<<MBT, 256>>>(SC, Ph, Pl);

  // ---- bypass = P * Vt^T (k-limit) ----
  gemm_mm<<<dim3(DD/128, TT/128, BB), 512, MM_SMEM>>>(
      Ph, Pl, TT, (long)TT*TT, Vth, Vtl, TT, (long)DD*TT, BYP, DD, (long)TT*DD,
      nullptr, nullptr, nullptr, nullptr, 0, TT, 3, EPI_PLAIN, 0, 1, 1.f,
      nullptr, nullptr, 0L, nullptr, 0L, nullptr);

  // ---- instr, novelty ----
  instr_k<<<MBT/8, 256>>>(Q, Wm_w, Wm_b, P_);
  novelty_k<<<MBT, 256>>>(V, G, SN, NOV);

  // ---- r_write ----
  gemm_mm<<<dim3(KK/128, MBT/128, 1), 512, MM_SMEM>>>(
      Qh, Ql, DD, 0L, WnTh, WnTl, DD, 0L, RW, KK, 0L, nullptr, nullptr, nullptr, nullptr, 0,
      DD, 3, EPI_RW, 0, 0, 1.f, Wn_b, NOV, 0L, WNC0, 0L, Wv_);

  // ---- RwT split, V_agg ----
  tsplit_kern<<<dim3(KK/32, TT/32, BB), dim3(32,8)>>>(RW, RwTh, RwTl, TT, KK);
  gemm_mm<<<dim3(DD/128, KK/128, BB), 512, MM_SMEM>>>(
      RwTh, RwTl, TT, (long)KK*TT, Vth, Vtl, TT, (long)DD*TT, VAG, DD, (long)KK*DD,
      VAGh, VAGl, nullptr, nullptr, 0, TT, 3, EPI_PLAIN, 0, 0, 1.f,
      nullptr, nullptr, 0L, nullptr, 0L, nullptr);

  // ================= 512-chain =================
  // AC = S*S^T + 1e-5I (3-term: source data for residuals)
  gemm_mm<<<dim3(KK/128, KK/128, 1), 512, MM_SMEM>>>(
      Sh, Sl, DD, 0L, Sh, Sl, DD, 0L, AC, KK, 0L,
      nullptr, nullptr, ACth, ACtl, KK, DD, 3, EPI_COV, 0, 0, 1.f,
      nullptr, nullptr, 0L, nullptr, 0L, nullptr);

  init_x0_k<<<KK*KK/256, 256>>>(XA, Xah, Xal, Xath, Xatl, 0.64f);

  // NS iterations single-term: quasi-stationary noise ~4e-3, squared to
  // ~1.6e-5 by the 3-term refinement below.
  float *cur=XA, *nxt=XB;
  __nv_bfloat16 *curh=Xah, *curl=Xal, *curth=Xath, *curtl=Xatl;
  __nv_bfloat16 *nxth=Xbh, *nxtl=Xbl, *nxtth=Xbth, *nxttl=Xbtl;
  for (int it=0; it<8; it++){
    gemm_mm<<<dim3(KK/128, KK/128, 1), 512, MM_SMEM>>>(
        curh, curl, KK, 0L, ACth, ACtl, KK, 0L, YT, KK, 0L,
        Yh, Yl, nullptr, nullptr, 0, KK, 1, EPI_PLAIN, 0, 0, 1.f,
        nullptr, nullptr, 0L, nullptr, 0L, nullptr);
    gemm_mm<<<dim3(KK/128, KK/128, 1), 512, MM_SMEM>>>(
        Yh, Yl, KK, 0L, curth, curtl, KK, 0L, nxt, KK, 0L,
        nxth, nxtl, nxtth, nxttl, KK, KK, 1, EPI_NS, 0, 0, 1.f,
        nullptr, cur, 0L, nullptr, 0L, nullptr);
    float* tf=cur; cur=nxt; nxt=tf;
    __nv_bfloat16* tb;
    tb=curh; curh=nxth; nxth=tb;   tb=curl; curl=nxtl; nxtl=tb;
    tb=curth; curth=nxtth; nxtth=tb; tb=curtl; curtl=nxttl; nxttl=tb;
  }

  // SV (3-term: its error enters the residual directly)
  gemm_mm<<<dim3(KK/128, KK/128, BB), 512, MM_SMEM>>>(
      VAGh, VAGl, DD, (long)KK*DD, Sh, Sl, DD, 0L, SV, KK, ZK2,
      SVh, SVl, nullptr, nullptr, 0, DD, 3, EPI_PLAIN, 0, 0, 1.f,
      nullptr, nullptr, 0L, nullptr, 0L, nullptr);
  // P2 = SV*X (1-term: refinement fixes it)
  gemm_mm<<<dim3(KK/128, KK/128, BB), 512, MM_SMEM>>>(
      SVh, SVl, KK, ZK2, curth, curtl, KK, 0L, P2, KK, ZK2,
      P2h, P2l, nullptr, nullptr, 0, KK, 1, EPI_PLAIN, 0, 0, 1.f,
      nullptr, nullptr, 0L, nullptr, 0L, nullptr);
  // R = SV - P2*AC (3-term: cancellation-critical)
  gemm_mm<<<dim3(KK/128, KK/128, BB), 512, MM_SMEM>>>(
      P2h, P2l, KK, ZK2, ACth, ACtl, KK, 0L, R4, KK, ZK2,
      R4h, R4l, nullptr, nullptr, 0, KK, 3, EPI_RSUB, 0, 0, 1.f,
      nullptr, SV, ZK2, nullptr, 0L, nullptr);
  // P2 += R*X (1-term: R is already small)
  gemm_mm<<<dim3(KK/128, KK/128, BB), 512, MM_SMEM>>>(
      R4h, R4l, KK, ZK2, curth, curtl, KK, 0L, P2, KK, ZK2,
      P2h, P2l, nullptr, nullptr, 0, KK, 1, EPI_ADD, 0, 0, 1.f,
      nullptr, P2, ZK2, nullptr, 0L, nullptr);

  // S_next (3-term)
  gemm_mm<<<dim3(DD/128, KK/128, BB), 512, MM_SMEM>>>(
      P2h, P2l, KK, ZK2, Sth, Stl, KK, 0L, outS, DD, (long)KK*DD,
      nullptr, nullptr, nullptr, nullptr, 0, KK, 3, EPI_SNEXT, 0, 0, 1.f,
      nullptr, S, 0L, VAG, (long)KK*DD, nullptr);

  // ---- topk + combine -> out ----
  topk_k<<<MBT, 128>>>(L, S, P_, BYP, out);
}

// round 17
// speedup vs baseline: 1.1373x; 1.0154x over previous
#include <cuda_runtime.h>
#include <cuda_bf16.h>
#include <cstdint>
#include <math.h>

typedef unsigned int u32;
typedef unsigned long long u64;

// ---------------- problem constants ----------------
#define BB 4
#define TT 2048
#define DD 1024
#define KK 512
#define KR 16

// ---------------- fp32 scratch ----------------
__device__ float g_Q[BB*TT*DD];
__device__ float g_V[BB*TT*DD];
__device__ float g_scores[(long)BB*TT*TT];
__device__ float g_byp[BB*TT*DD];
__device__ float g_L[BB*TT*KK];
__device__ float g_G[BB*TT*KK];
__device__ float g_Rw[BB*TT*KK];
__device__ float g_Vagg[BB*KK*DD];
__device__ float g_SV[BB*KK*KK];
__device__ float g_P2[BB*KK*KK];
__device__ float g_R4[BB*KK*KK];
__device__ float g_Acov[KK*KK];
__device__ float g_Xa[KK*KK];
__device__ float g_Xb[KK*KK];
__device__ float g_Yt[KK*KK];
__device__ float g_Wnc0[KK];
__device__ float g_w[TT];
__device__ float g_snorm[KK];
__device__ float g_nov[BB*TT];
__device__ float g_p[BB*TT];
__device__ float g_SnextScratch[BB*KK*DD];

// ---------------- bf16 split scratch ----------------
__device__ __nv_bfloat16 g_xh[BB*TT*DD];
__device__ __nv_bfloat16 g_xl[BB*TT*DD];
__device__ __nv_bfloat16 g_Qh[BB*TT*DD];
__device__ __nv_bfloat16 g_Ql[BB*TT*DD];
__device__ __nv_bfloat16 g_Vh[BB*TT*DD];
__device__ __nv_bfloat16 g_Vl[BB*TT*DD];
__device__ __nv_bfloat16 g_Vth[BB*DD*TT];
__device__ __nv_bfloat16 g_Vtl[BB*DD*TT];
__device__ __nv_bfloat16 g_Ph[(long)BB*TT*TT];
__device__ __nv_bfloat16 g_Pl[(long)BB*TT*TT];
__device__ __nv_bfloat16 g_Sh[KK*DD];
__device__ __nv_bfloat16 g_Sl[KK*DD];
__device__ __nv_bfloat16 g_Sth[DD*KK];
__device__ __nv_bfloat16 g_Stl[DD*KK];
__device__ __nv_bfloat16 g_Wqh[DD*DD];
__device__ __nv_bfloat16 g_Wql[DD*DD];
__device__ __nv_bfloat16 g_Wvh[DD*DD];
__device__ __nv_bfloat16 g_Wvl[DD*DD];
__device__ __nv_bfloat16 g_WnTh[KK*DD];
__device__ __nv_bfloat16 g_WnTl[KK*DD];
__device__ __nv_bfloat16 g_RwTh[BB*KK*TT];
__device__ __nv_bfloat16 g_RwTl[BB*KK*TT];
__device__ __nv_bfloat16 g_P2h[BB*KK*KK];
__device__ __nv_bfloat16 g_P2l[BB*KK*KK];
// chain operand forms
__device__ __nv_bfloat16 g_ACth[KK*KK];
__device__ __nv_bfloat16 g_ACtl[KK*KK];
__device__ __nv_bfloat16 g_Yh[KK*KK];
__device__ __nv_bfloat16 g_Yl[KK*KK];
__device__ __nv_bfloat16 g_Xah[KK*KK];
__device__ __nv_bfloat16 g_Xal[KK*KK];
__device__ __nv_bfloat16 g_Xath[KK*KK];
__device__ __nv_bfloat16 g_Xatl[KK*KK];
__device__ __nv_bfloat16 g_Xbh[KK*KK];
__device__ __nv_bfloat16 g_Xbl[KK*KK];
__device__ __nv_bfloat16 g_Xbth[KK*KK];
__device__ __nv_bfloat16 g_Xbtl[KK*KK];
__device__ __nv_bfloat16 g_VAGh[BB*KK*DD];
__device__ __nv_bfloat16 g_VAGl[BB*KK*DD];
__device__ __nv_bfloat16 g_SVh[BB*KK*KK];
__device__ __nv_bfloat16 g_SVl[BB*KK*KK];
__device__ __nv_bfloat16 g_R4h[BB*KK*KK];
__device__ __nv_bfloat16 g_R4l[BB*KK*KK];

// ---------------- reductions ----------------
__device__ __forceinline__ float warpReduceSum(float v){
  #pragma unroll
  for (int o=16;o;o>>=1) v += __shfl_xor_sync(0xffffffffu, v, o);
  return v;
}
__device__ __forceinline__ float warpReduceMax(float v){
  #pragma unroll
  for (int o=16;o;o>>=1) v = fmaxf(v, __shfl_xor_sync(0xffffffffu, v, o));
  return v;
}
__device__ float blockReduceSum(float v){
  __shared__ float sh[33];
  int lane = threadIdx.x & 31, wid = threadIdx.x >> 5, nw = blockDim.x >> 5;
  v = warpReduceSum(v);
  __syncthreads();
  if (lane==0) sh[wid]=v;
  __syncthreads();
  if (wid==0){
    float r = (lane<nw)? sh[lane] : 0.f;
    r = warpReduceSum(r);
    if (lane==0) sh[32]=r;
  }
  __syncthreads();
  return sh[32];
}
__device__ float blockReduceMax(float v){
  __shared__ float sh[33];
  int lane = threadIdx.x & 31, wid = threadIdx.x >> 5, nw = blockDim.x >> 5;
  v = warpReduceMax(v);
  __syncthreads();
  if (lane==0) sh[wid]=v;
  __syncthreads();
  if (wid==0){
    float r = (lane<nw)? sh[lane] : -INFINITY;
    r = warpReduceMax(r);
    if (lane==0) sh[32]=r;
  }
  __syncthreads();
  return sh[32];
}

// ================= mma.sync helpers =================
__device__ __forceinline__ void ldsm4(u32& r0, u32& r1, u32& r2, u32& r3, u32 saddr){
  asm volatile("ldmatrix.sync.aligned.m8n8.x4.shared.b16 {%0,%1,%2,%3}, [%4];"
    : "=r"(r0), "=r"(r1), "=r"(r2), "=r"(r3) : "r"(saddr));
}
__device__ __forceinline__ void mma16816(float* c, const u32* a, const u32* b){
  asm volatile(
    "mma.sync.aligned.m16n8k16.row.col.f32.bf16.bf16.f32 "
    "{%0,%1,%2,%3}, {%4,%5,%6,%7}, {%8,%9}, {%0,%1,%2,%3};"
    : "+f"(c[0]), "+f"(c[1]), "+f"(c[2]), "+f"(c[3])
    : "r"(a[0]), "r"(a[1]), "r"(a[2]), "r"(a[3]), "r"(b[0]), "r"(b[1]));
}
__device__ __forceinline__ void cpasync16(u32 dst, const void* src){
  asm volatile("cp.async.cg.shared.global [%0], [%1], 16;" :: "r"(dst), "l"(src));
}

// epilogue codes
#define EPI_PLAIN 0
#define EPI_BIAS  1
#define EPI_COV   2
#define EPI_RW    3
#define EPI_NS    4
#define EPI_SNEXT 5
#define EPI_RSUB  6
#define EPI_ADD   7

#define ROWB 144
#define ARR_B (128*ROWB)
#define ST_B  (4*ARR_B)
#define MM_SMEM (2*ST_B)

// ================= bf16 split NT GEMM via mma.sync: C = A*B^T =================
// 512 thr (4x4 warps), 128x128 tile, BK=64, 2-stage cp.async pipeline,
// frag double-buffer + term-major MMA. nterms: 3 = full split (~1e-5), 1 =
// hi*hi only (~4e-3; noise-tolerant consumers). Optional outputs: fp32 C,
// bf16 splits Coh/Col, transposed splits Cth/Ctl (ld = ldt, z-stride = sC).
__global__ void __launch_bounds__(512)
gemm_mm(const __nv_bfloat16* Ah, const __nv_bfloat16* Al, int lda, long sA,
        const __nv_bfloat16* Bh, const __nv_bfloat16* Bl, int ldb, long sB,
        float* C, int ldc, long sC,
        __nv_bfloat16* Coh, __nv_bfloat16* Col,
        __nv_bfloat16* Cth, __nv_bfloat16* Ctl, int ldt,
        int Kd, int nterms, int epi, int cskip, int klim, float alpha,
        const float* bias, const float* aux1, long s1,
        const float* aux2, long s2, const float* rowv)
{
  if (cskip && (int)blockIdx.x > (int)blockIdx.y) return;
  extern __shared__ __nv_bfloat16 dynsm[];

  const int tid  = threadIdx.x;
  const int lane = tid & 31;
  const int warp = tid >> 5;
  const int wm = warp >> 2, wn = warp & 3;
  const int m0 = blockIdx.y*128, n0 = blockIdx.x*128;
  const long z = blockIdx.z;
  Ah += z*sA; Al += z*sA; Bh += z*sB; Bl += z*sB; C += z*sC;
  const float* ax1 = aux1 ? aux1 + z*s1 : aux1;
  const float* ax2 = aux2 ? aux2 + z*s2 : aux2;

  const u32 sm0 = (u32)__cvta_generic_to_shared(dynsm);

  float acc[2][4][4];
  #pragma unroll
  for (int i=0;i<2;i++)
    #pragma unroll
    for (int j=0;j<4;j++)
      #pragma unroll
      for (int q=0;q<4;q++) acc[i][j][q] = 0.f;

  const int kend = klim ? min(Kd, m0+128) : Kd;
  const int nch  = kend >> 6;
  const bool full = (nterms == 3);

  const int lr = tid >> 2;
  const int lq = (tid & 3) * 16;
  const __nv_bfloat16* gA_h = Ah + (long)(m0+lr)*lda + lq;
  const __nv_bfloat16* gA_l = Al + (long)(m0+lr)*lda + lq;
  const __nv_bfloat16* gB_h = Bh + (long)(n0+lr)*ldb + lq;
  const __nv_bfloat16* gB_l = Bl + (long)(n0+lr)*ldb + lq;
  const u32 dst0 = sm0 + lr*ROWB + lq*2;

  auto issue_chunk = [&](int cc, int ss){
    int k0 = cc << 6;
    u32 dst = dst0 + ss*ST_B;
    cpasync16(dst,                gA_h + k0);
    cpasync16(dst + 16,           gA_h + k0 + 8);
    cpasync16(dst + 2*ARR_B,      gB_h + k0);
    cpasync16(dst + 2*ARR_B + 16, gB_h + k0 + 8);
    if (full){
      cpasync16(dst +   ARR_B,      gA_l + k0);
      cpasync16(dst +   ARR_B + 16, gA_l + k0 + 8);
      cpasync16(dst + 3*ARR_B,      gB_l + k0);
      cpasync16(dst + 3*ARR_B + 16, gB_l + k0 + 8);
    }
    asm volatile("cp.async.commit_group;" ::: "memory");
  };

  issue_chunk(0, 0);

  u32 fa_h[2][2][4], fa_l[2][2][4];
  u32 fb_h[2][4][2], fb_l[2][4][2];

  const int ga  = lane >> 3;
  const int ar_ = (ga & 1)*8 + (lane & 7);
  const int br_ = (ga >> 1)*8 + (lane & 7);

  for (int c=0; c<nch; c++){
    asm volatile("cp.async.wait_group 0;" ::: "memory");
    __syncthreads();
    if (c+1 < nch) issue_chunk(c+1, (c+1)&1);

    const u32 sbase = sm0 + (c&1)*ST_B;

    {
      int ac = (ga >> 1)*8;
      #pragma unroll
      for (int mt=0; mt<2; mt++){
        u32 sa = sbase + (wm*32 + mt*16 + ar_)*ROWB + ac*2;
        ldsm4(fa_h[0][mt][0], fa_h[0][mt][1], fa_h[0][mt][2], fa_h[0][mt][3], sa);
        if (full)
          ldsm4(fa_l[0][mt][0], fa_l[0][mt][1], fa_l[0][mt][2], fa_l[0][mt][3], sa + ARR_B);
      }
      int bc = (ga & 1)*8;
      #pragma unroll
      for (int pr=0; pr<2; pr++){
        u32 sb = sbase + 2*ARR_B + (wn*32 + pr*16 + br_)*ROWB + bc*2;
        ldsm4(fb_h[0][pr*2][0], fb_h[0][pr*2][1], fb_h[0][pr*2+1][0], fb_h[0][pr*2+1][1], sb);
        if (full)
          ldsm4(fb_l[0][pr*2][0], fb_l[0][pr*2][1], fb_l[0][pr*2+1][0], fb_l[0][pr*2+1][1], sb + ARR_B);
      }
    }

    #pragma unroll
    for (int i=0; i<4; i++){
      const int cb = i & 1, nb = cb ^ 1;
      if (i < 3){
        int kk = (i+1) << 4;
        int ac = kk + (ga >> 1)*8;
        #pragma unroll
        for (int mt=0; mt<2; mt++){
          u32 sa = sbase + (wm*32 + mt*16 + ar_)*ROWB + ac*2;
          ldsm4(fa_h[nb][mt][0], fa_h[nb][mt][1], fa_h[nb][mt][2], fa_h[nb][mt][3], sa);
          if (full)
            ldsm4(fa_l[nb][mt][0], fa_l[nb][mt][1], fa_l[nb][mt][2], fa_l[nb][mt][3], sa + ARR_B);
        }
        int bc = kk + (ga & 1)*8;
        #pragma unroll
        for (int pr=0; pr<2; pr++){
          u32 sb = sbase + 2*ARR_B + (wn*32 + pr*16 + br_)*ROWB + bc*2;
          ldsm4(fb_h[nb][pr*2][0], fb_h[nb][pr*2][1], fb_h[nb][pr*2+1][0], fb_h[nb][pr*2+1][1], sb);
          if (full)
            ldsm4(fb_l[nb][pr*2][0], fb_l[nb][pr*2][1], fb_l[nb][pr*2+1][0], fb_l[nb][pr*2+1][1], sb + ARR_B);
        }
      }
      #pragma unroll
      for (int mt=0; mt<2; mt++)
        #pragma unroll
        for (int nt=0; nt<4; nt++)
          mma16816(acc[mt][nt], fa_h[cb][mt], fb_h[cb][nt]);
      if (full){
        #pragma unroll
        for (int mt=0; mt<2; mt++)
          #pragma unroll
          for (int nt=0; nt<4; nt++)
            mma16816(acc[mt][nt], fa_h[cb][mt], fb_l[cb][nt]);
        #pragma unroll
        for (int mt=0; mt<2; mt++)
          #pragma unroll
          for (int nt=0; nt<4; nt++)
            mma16816(acc[mt][nt], fa_l[cb][mt], fb_h[cb][nt]);
      }
    }
  }

  // ---- epilogue ----
  const int gr = lane >> 2;
  const int tc = (lane & 3) * 2;
  #pragma unroll
  for (int mt=0; mt<2; mt++){
    #pragma unroll
    for (int h=0; h<2; h++){
      int r = m0 + wm*32 + mt*16 + h*8 + gr;
      float* Crow = C + (long)r*ldc;
      #pragma unroll
      for (int nt=0; nt<4; nt++){
        int ccol = n0 + wn*32 + nt*8 + tc;
        float v0 = acc[mt][nt][h*2], v1 = acc[mt][nt][h*2+1];
        if (epi == EPI_PLAIN){
          v0 *= alpha; v1 *= alpha;
        } else if (epi == EPI_BIAS){
          v0 += bias[ccol]; v1 += bias[ccol+1];
        } else if (epi == EPI_RW){
          float a1r = ax1[r], rv = rowv[r & (TT-1)];
          float x0 = v0 + a1r*ax2[ccol]   + bias[ccol];
          float x1 = v1 + a1r*ax2[ccol+1] + bias[ccol+1];
          v0 = rv / (1.f + expf(-x0));
          v1 = rv / (1.f + expf(-x1));
        } else if (epi == EPI_SNEXT){
          v0 = 0.99f*ax1[(long)r*ldc + ccol]   + 0.1f*(ax2[(long)r*ldc + ccol]   - v0);
          v1 = 0.99f*ax1[(long)r*ldc + ccol+1] + 0.1f*(ax2[(long)r*ldc + ccol+1] - v1);
        } else if (epi == EPI_COV){
          if (r == ccol)   v0 += 1e-5f;
          if (r == ccol+1) v1 += 1e-5f;
        } else if (epi == EPI_NS){
          v0 = 2.f*ax1[(long)r*ldc + ccol]   - v0;
          v1 = 2.f*ax1[(long)r*ldc + ccol+1] - v1;
        } else if (epi == EPI_RSUB){
          v0 = ax1[(long)r*ldc + ccol]   - v0;
          v1 = ax1[(long)r*ldc + ccol+1] - v1;
        } else if (epi == EPI_ADD){
          v0 = ax1[(long)r*ldc + ccol]   + v0;
          v1 = ax1[(long)r*ldc + ccol+1] + v1;
        }
        *(float2*)(Crow + ccol) = make_float2(v0, v1);
        __nv_bfloat16 h0, h1, l0, l1;
        if (Coh || Cth){
          h0 = __float2bfloat16(v0);
          h1 = __float2bfloat16(v1);
          l0 = __float2bfloat16(v0 - __bfloat162float(h0));
          l1 = __float2bfloat16(v1 - __bfloat162float(h1));
        }
        if (Coh){
          *(__nv_bfloat162*)(Coh + z*sC + (long)r*ldc + ccol) = __halves2bfloat162(h0, h1);
          *(__nv_bfloat162*)(Col + z*sC + (long)r*ldc + ccol) = __halves2bfloat162(l0, l1);
        }
        if (Cth){
          Cth[z*sC + (long)ccol*ldt + r]     = h0;
          Ctl[z*sC + (long)ccol*ldt + r]     = l0;
          Cth[z*sC + (long)(ccol+1)*ldt + r] = h1;
          Ctl[z*sC + (long)(ccol+1)*ldt + r] = l1;
        }
      }
    }
  }
}

// ---------------- elementwise / prep kernels ----------------
__global__ void split_kern(const float* __restrict__ X, __nv_bfloat16* __restrict__ H,
                           __nv_bfloat16* __restrict__ Lo, long n){
  long i = (long)blockIdx.x*256 + threadIdx.x;
  if (i < n){
    float v = X[i];
    __nv_bfloat16 h = __float2bfloat16(v);
    H[i] = h;
    Lo[i] = __float2bfloat16(v - __bfloat162float(h));
  }
}

__global__ void tsplit_kern(const float* __restrict__ X, __nv_bfloat16* __restrict__ TH,
                            __nv_bfloat16* __restrict__ TL, int R, int Cc){
  __shared__ float tile[32][33];
  const float* Xz = X + (long)blockIdx.z*R*Cc;
  __nv_bfloat16* THz = TH + (long)blockIdx.z*R*Cc;
  __nv_bfloat16* TLz = TL + (long)blockIdx.z*R*Cc;
  int c0 = blockIdx.x*32, r0 = blockIdx.y*32;
  int tx = threadIdx.x, ty = threadIdx.y;
  for (int i=ty; i<32; i+=8)
    tile[i][tx] = Xz[(long)(r0+i)*Cc + c0 + tx];
  __syncthreads();
  for (int i=ty; i<32; i+=8){
    float v = tile[tx][i];
    __nv_bfloat16 h = __float2bfloat16(v);
    long o = (long)(c0+i)*R + r0 + tx;
    THz[o] = h;
    TLz[o] = __float2bfloat16(v - __bfloat162float(h));
  }
}

__global__ void pack_wn_k(const float* __restrict__ Wn, __nv_bfloat16* __restrict__ H,
                          __nv_bfloat16* __restrict__ Lo, float* __restrict__ c0){
  long i = (long)blockIdx.x*256 + threadIdx.x;
  if (i < (long)KK*DD){
    int k = (int)(i >> 10), d = (int)(i & 1023);
    float v = Wn[(long)k*(DD+1) + 1 + d];
    __nv_bfloat16 h = __float2bfloat16(v);
    H[i] = h;
    Lo[i] = __float2bfloat16(v - __bfloat162float(h));
    if (d==0) c0[k] = Wn[(long)k*(DD+1)];
  }
}

__global__ void prep_w_k(float* __restrict__ w){
  int t = blockIdx.x*256 + threadIdx.x;
  if (t < TT){
    double z = (1.0 - pow(0.99, (double)TT)) / 0.01;
    w[t] = (float)(pow(0.99, (double)(TT-1-t)) / z);
  }
}

__global__ void snorm_k(const float* __restrict__ S, float* __restrict__ sn){
  int k = blockIdx.x*8 + (threadIdx.x>>5);
  int lane = threadIdx.x & 31;
  float s = 0.f;
  const float4* row = (const float4*)(S + (long)k*DD);
  for (int i=lane; i<DD/4; i+=32){ float4 a = row[i]; s += a.x*a.x+a.y*a.y+a.z*a.z+a.w*a.w; }
  s = warpReduceSum(s);
  if (lane==0) sn[k] = fmaxf(sqrtf(s), 1e-8f);
}

__global__ void init_x0_k(float* __restrict__ X,
                          __nv_bfloat16* __restrict__ Xh, __nv_bfloat16* __restrict__ Xl,
                          __nv_bfloat16* __restrict__ Xth, __nv_bfloat16* __restrict__ Xtl,
                          float alpha){
  int i = blockIdx.x*256 + threadIdx.x;
  int r = i >> 9, c = i & (KK-1);
  float v = (r==c) ? alpha : 0.f;
  X[i] = v;
  __nv_bfloat16 h = __float2bfloat16(v);
  __nv_bfloat16 l = __float2bfloat16(v - __bfloat162float(h));
  Xh[i] = h; Xl[i] = l;
  long t = (long)c*KK + r;
  Xth[t] = h; Xtl[t] = l;
}

__global__ void instr_k(const float* __restrict__ Q, const float* __restrict__ Wm,
                        const float* __restrict__ Wmb, float* __restrict__ p){
  int m = blockIdx.x*8 + (threadIdx.x>>5);
  int lane = threadIdx.x & 31;
  const float4* q = (const float4*)(Q + (long)m*DD);
  const float4* w = (const float4*)Wm;
  float acc = 0.f;
  for (int i=lane; i<DD/4; i+=32){
    float4 a=q[i], b=w[i];
    acc += a.x*b.x + a.y*b.y + a.z*b.z + a.w*b.w;
  }
  acc = warpReduceSum(acc);
  if (lane==0){
    p[m] = 1.f/(1.f+expf(-(acc + Wmb[0])));
  }
}

__global__ void novelty_k(const float* __restrict__ V, const float* __restrict__ G,
                          const float* __restrict__ sn, float* __restrict__ nov){
  int m = blockIdx.x;
  float s = 0.f;
  for (int d=threadIdx.x; d<DD; d+=256){ float x = V[(long)m*DD+d]; s += x*x; }
  s = blockReduceSum(s);
  float vn = fmaxf(sqrtf(s), 1e-8f);
  float mx = -INFINITY;
  for (int k=threadIdx.x; k<KK; k+=256) mx = fmaxf(mx, G[(long)m*KK+k] / (vn*sn[k]));
  mx = blockReduceMax(mx);
  if (threadIdx.x==0) nov[m] = 1.f - mx;
}

__global__ void softmax_k(const float* __restrict__ sc,
                          __nv_bfloat16* __restrict__ Ph, __nv_bfloat16* __restrict__ Pl){
  int m = blockIdx.x;
  int q = m & (TT-1);
  const float* row = sc + (long)m*TT;
  __nv_bfloat16* ph = Ph + (long)m*TT;
  __nv_bfloat16* pl = Pl + (long)m*TT;
  int len = q+1;
  int kend = ((q>>7)+1) << 7;
  float mx = -INFINITY;
  for (int k=threadIdx.x; k<len; k+=256) mx = fmaxf(mx, row[k]);
  mx = blockReduceMax(mx);
  float s = 0.f;
  for (int k=threadIdx.x; k<len; k+=256) s += expf(row[k]-mx);
  s = blockReduceSum(s);
  float inv = 1.f/s;
  for (int k=threadIdx.x; k<kend; k+=256){
    float p = (k<len) ? expf(row[k]-mx)*inv : 0.f;
    __nv_bfloat16 h = __float2bfloat16(p);
    ph[k] = h;
    pl[k] = __float2bfloat16(p - __bfloat162float(h));
  }
}

__global__ void __launch_bounds__(128)
topk_k(const float* __restrict__ L, const float* __restrict__ S,
       const float* __restrict__ p_, const float* __restrict__ byp,
       float* __restrict__ out){
  __shared__ float ls[KK];
  __shared__ float tv[KR];
  __shared__ int   ti[KR];
  __shared__ float wv[4];
  __shared__ int   wi[4];
  __shared__ float probs[KR];
  int m = blockIdx.x, tid = threadIdx.x;
  for (int k=tid; k<KK; k+=128) ls[k] = L[(long)m*KK + k];
  __syncthreads();
  for (int it=0; it<KR; it++){
    float bv = -INFINITY; int bi = 0;
    #pragma unroll
    for (int u=0; u<KK/128; u++){
      int k = tid + u*128;
      float x = ls[k];
      if (x > bv){ bv = x; bi = k; }
    }
    #pragma unroll
    for (int o=16;o;o>>=1){
      float ov = __shfl_xor_sync(0xffffffffu, bv, o);
      int   oi = __shfl_xor_sync(0xffffffffu, bi, o);
      if (ov > bv){ bv = ov; bi = oi; }
    }
    if ((tid&31)==0){ wv[tid>>5]=bv; wi[tid>>5]=bi; }
    __syncthreads();
    if (tid==0){
      float b2 = wv[0]; int i2 = wi[0];
      #pragma unroll
      for (int w=1;w<4;w++) if (wv[w]>b2){ b2=wv[w]; i2=wi[w]; }
      tv[it]=b2; ti[it]=i2; ls[i2]=-INFINITY;
    }
    __syncthreads();
  }
  if (tid==0){
    float mx = tv[0], s = 0.f, e[KR];
    #pragma unroll
    for (int j=0;j<KR;j++){ e[j]=expf(tv[j]-mx); s+=e[j]; }
    float inv = 1.f/s;
    #pragma unroll
    for (int j=0;j<KR;j++) probs[j]=e[j]*inv;
  }
  __syncthreads();
  float pm = p_[m];
  for (int d=tid; d<DD; d+=128){
    float c = 0.f;
    #pragma unroll
    for (int j=0;j<KR;j++) c = fmaf(probs[j], S[(long)ti[j]*DD + d], c);
    out[(long)m*DD + d] = (1.f-pm)*c + pm*byp[(long)m*DD + d];
  }
}

// ---------------- host ----------------
static void* getsym(const void* sym){
  void* p = nullptr;
  cudaGetSymbolAddress(&p, sym);
  return p;
}
#define BF16P(sym) ((__nv_bfloat16*)getsym(sym))

extern "C" void kernel_launch(void* const* d_in, const int* in_sizes, int n_in,
                              void* d_out, int out_size){
  const float* x    = (const float*)d_in[0];
  const float* S    = (const float*)d_in[1];
  const float* Wq_b = (const float*)d_in[3];
  const float* Wv_b = (const float*)d_in[5];
  const float* Wn_w = (const float*)d_in[6];
  const float* Wn_b = (const float*)d_in[7];
  const float* Wm_w = (const float*)d_in[8];
  const float* Wm_b = (const float*)d_in[9];
  float* out = (float*)d_out;

  float* Q    = (float*)getsym(g_Q);
  float* V    = (float*)getsym(g_V);
  float* SC   = (float*)getsym(g_scores);
  float* BYP  = (float*)getsym(g_byp);
  float* L    = (float*)getsym(g_L);
  float* G    = (float*)getsym(g_G);
  float* RW   = (float*)getsym(g_Rw);
  float* VAG  = (float*)getsym(g_Vagg);
  float* SV   = (float*)getsym(g_SV);
  float* P2   = (float*)getsym(g_P2);
  float* R4   = (float*)getsym(g_R4);
  float* AC   = (float*)getsym(g_Acov);
  float* XA   = (float*)getsym(g_Xa);
  float* XB   = (float*)getsym(g_Xb);
  float* YT   = (float*)getsym(g_Yt);
  float* WNC0 = (float*)getsym(g_Wnc0);
  float* Wv_  = (float*)getsym(g_w);
  float* SN   = (float*)getsym(g_snorm);
  float* NOV  = (float*)getsym(g_nov);
  float* P_   = (float*)getsym(g_p);
  float* SNS  = (float*)getsym(g_SnextScratch);

  __nv_bfloat16 *xh=BF16P(g_xh), *xl=BF16P(g_xl);
  __nv_bfloat16 *Qh=BF16P(g_Qh), *Ql=BF16P(g_Ql);
  __nv_bfloat16 *Vh=BF16P(g_Vh), *Vl=BF16P(g_Vl);
  __nv_bfloat16 *Vth=BF16P(g_Vth), *Vtl=BF16P(g_Vtl);
  __nv_bfloat16 *Ph=BF16P(g_Ph), *Pl=BF16P(g_Pl);
  __nv_bfloat16 *Sh=BF16P(g_Sh), *Sl=BF16P(g_Sl);
  __nv_bfloat16 *Sth=BF16P(g_Sth), *Stl=BF16P(g_Stl);
  __nv_bfloat16 *Wqh=BF16P(g_Wqh), *Wql=BF16P(g_Wql);
  __nv_bfloat16 *Wvh=BF16P(g_Wvh), *Wvl=BF16P(g_Wvl);
  __nv_bfloat16 *WnTh=BF16P(g_WnTh), *WnTl=BF16P(g_WnTl);
  __nv_bfloat16 *RwTh=BF16P(g_RwTh), *RwTl=BF16P(g_RwTl);
  __nv_bfloat16 *P2h=BF16P(g_P2h), *P2l=BF16P(g_P2l);
  __nv_bfloat16 *ACth=BF16P(g_ACth), *ACtl=BF16P(g_ACtl);
  __nv_bfloat16 *Yh=BF16P(g_Yh), *Yl=BF16P(g_Yl);
  __nv_bfloat16 *Xah=BF16P(g_Xah), *Xal=BF16P(g_Xal);
  __nv_bfloat16 *Xath=BF16P(g_Xath), *Xatl=BF16P(g_Xatl);
  __nv_bfloat16 *Xbh=BF16P(g_Xbh), *Xbl=BF16P(g_Xbl);
  __nv_bfloat16 *Xbth=BF16P(g_Xbth), *Xbtl=BF16P(g_Xbtl);
  __nv_bfloat16 *VAGh=BF16P(g_VAGh), *VAGl=BF16P(g_VAGl);
  __nv_bfloat16 *SVh=BF16P(g_SVh), *SVl=BF16P(g_SVl);
  __nv_bfloat16 *R4h=BF16P(g_R4h), *R4l=BF16P(g_R4l);

  const long outElems = (long)BB*TT*DD + (long)BB*KK*DD;
  float* outS = (out_size >= outElems) ? out + (long)BB*TT*DD : SNS;

  const float rsqD = 0.03125f;
  const int MBT = BB*TT;
  const long ZK2 = (long)KK*KK;
  const long ZTD = (long)TT*DD;
  const long ZTK = (long)TT*KK;

  cudaFuncSetAttribute(gemm_mm, cudaFuncAttributeMaxDynamicSharedMemorySize, MM_SMEM);

  // ---- prep ordered so my launch #4 is a big gemm_mm (ncu capture slot) ----
  split_kern<<<(BB*TT*DD+255)/256, 256>>>(x, xh, xl, (long)BB*TT*DD);
  split_kern<<<(DD*DD+255)/256, 256>>>((const float*)d_in[2], Wqh, Wql, (long)DD*DD);
  split_kern<<<(DD*DD+255)/256, 256>>>((const float*)d_in[4], Wvh, Wvl, (long)DD*DD);
  gemm_mm<<<dim3(DD/128, MBT/128, 1), 512, MM_SMEM>>>(
      xh, xl, DD, 0L, Wqh, Wql, DD, 0L, Q, DD, 0L, Qh, Ql, nullptr, nullptr, 0,
      DD, 3, EPI_BIAS, 0, 0, 1.f, Wq_b, nullptr, 0L, nullptr, 0L, nullptr);
  // V projection, z-batched: emits V fp32 + Vh/Vl + TRANSPOSED Vth/Vtl
  gemm_mm<<<dim3(DD/128, TT/128, BB), 512, MM_SMEM>>>(
      xh, xl, DD, ZTD, Wvh, Wvl, DD, 0L, V, DD, ZTD, Vh, Vl, Vth, Vtl, TT,
      DD, 3, EPI_BIAS, 0, 0, 1.f, Wv_b, nullptr, 0L, nullptr, 0L, nullptr);

  // ---- remaining prep ----
  split_kern<<<(KK*DD+255)/256, 256>>>(S, Sh, Sl, (long)KK*DD);
  tsplit_kern<<<dim3(DD/32, KK/32, 1), dim3(32,8)>>>(S, Sth, Stl, KK, DD);
  pack_wn_k<<<(KK*DD+255)/256, 256>>>(Wn_w, WnTh, WnTl, WNC0);
  prep_w_k<<<(TT+255)/256, 256>>>(Wv_);
  snorm_k<<<KK/8, 256>>>(S, SN);

  // ---- L = Q*S^T/32 (3-term) ; G = V*S^T (1-term: feeds only novelty max) ----
  gemm_mm<<<dim3(KK/128, MBT/128, 1), 512, MM_SMEM>>>(
      Qh, Ql, DD, 0L, Sh, Sl, DD, 0L, L, KK, 0L, nullptr, nullptr, nullptr, nullptr, 0,
      DD, 3, EPI_PLAIN, 0, 0, rsqD, nullptr, nullptr, 0L, nullptr, 0L, nullptr);
  gemm_mm<<<dim3(KK/128, MBT/128, 1), 512, MM_SMEM>>>(
      Vh, Vl, DD, 0L, Sh, Sl, DD, 0L, G, KK, 0L, nullptr, nullptr, nullptr, nullptr, 0,
      DD, 1, EPI_PLAIN, 0, 0, 1.f, nullptr, nullptr, 0L, nullptr, 0L, nullptr);

  // ---- causal scores ----
  gemm_mm<<<dim3(TT/128, TT/128, BB), 512, MM_SMEM>>>(
      Qh, Ql, DD, ZTD, Qh, Ql, DD, ZTD, SC, TT, (long)TT*TT,
      nullptr, nullptr, nullptr, nullptr, 0, DD, 3, EPI_PLAIN, 1, 0, rsqD,
      nullptr, nullptr, 0L, nullptr, 0L, nullptr);

  // ---- softmax -> split-bf16 P ----
  softmax_k<<<MBT, 256>>>(SC, Ph, Pl);

  // ---- bypass = P * Vt^T (k-limit) ----
  gemm_mm<<<dim3(DD/128, TT/128, BB), 512, MM_SMEM>>>(
      Ph, Pl, TT, (long)TT*TT, Vth, Vtl, TT, (long)DD*TT, BYP, DD, ZTD,
      nullptr, nullptr, nullptr, nullptr, 0, TT, 3, EPI_PLAIN, 0, 1, 1.f,
      nullptr, nullptr, 0L, nullptr, 0L, nullptr);

  // ---- instr, novelty ----
  instr_k<<<MBT/8, 256>>>(Q, Wm_w, Wm_b, P_);
  novelty_k<<<MBT, 256>>>(V, G, SN, NOV);

  // ---- r_write, z-batched: emits RW fp32 + TRANSPOSED RwTh/RwTl ----
  gemm_mm<<<dim3(KK/128, TT/128, BB), 512, MM_SMEM>>>(
      Qh, Ql, DD, ZTD, WnTh, WnTl, DD, 0L, RW, KK, ZTK,
      nullptr, nullptr, RwTh, RwTl, TT,
      DD, 3, EPI_RW, 0, 0, 1.f, Wn_b, NOV, (long)TT, WNC0, 0L, Wv_);

  // ---- V_agg = RwT * Vt^T ----
  gemm_mm<<<dim3(DD/128, KK/128, BB), 512, MM_SMEM>>>(
      RwTh, RwTl, TT, ZTK, Vth, Vtl, TT, (long)DD*TT, VAG, DD, (long)KK*DD,
      VAGh, VAGl, nullptr, nullptr, 0, TT, 3, EPI_PLAIN, 0, 0, 1.f,
      nullptr, nullptr, 0L, nullptr, 0L, nullptr);

  // ================= 512-chain =================
  gemm_mm<<<dim3(KK/128, KK/128, 1), 512, MM_SMEM>>>(
      Sh, Sl, DD, 0L, Sh, Sl, DD, 0L, AC, KK, 0L,
      nullptr, nullptr, ACth, ACtl, KK, DD, 3, EPI_COV, 0, 0, 1.f,
      nullptr, nullptr, 0L, nullptr, 0L, nullptr);

  init_x0_k<<<KK*KK/256, 256>>>(XA, Xah, Xal, Xath, Xatl, 0.64f);

  // NS 1-term; residual floor ~4e-3 squared to ~1.6e-5 by 3-term refinement.
  float *cur=XA, *nxt=XB;
  __nv_bfloat16 *curh=Xah, *curl=Xal, *curth=Xath, *curtl=Xatl;
  __nv_bfloat16 *nxth=Xbh, *nxtl=Xbl, *nxtth=Xbth, *nxttl=Xbtl;
  for (int it=0; it<7; it++){
    gemm_mm<<<dim3(KK/128, KK/128, 1), 512, MM_SMEM>>>(
        curh, curl, KK, 0L, ACth, ACtl, KK, 0L, YT, KK, 0L,
        Yh, Yl, nullptr, nullptr, 0, KK, 1, EPI_PLAIN, 0, 0, 1.f,
        nullptr, nullptr, 0L, nullptr, 0L, nullptr);
    gemm_mm<<<dim3(KK/128, KK/128, 1), 512, MM_SMEM>>>(
        Yh, Yl, KK, 0L, curth, curtl, KK, 0L, nxt, KK, 0L,
        nxth, nxtl, nxtth, nxttl, KK, KK, 1, EPI_NS, 0, 0, 1.f,
        nullptr, cur, 0L, nullptr, 0L, nullptr);
    float* tf=cur; cur=nxt; nxt=tf;
    __nv_bfloat16* tb;
    tb=curh; curh=nxth; nxth=tb;   tb=curl; curl=nxtl; nxtl=tb;
    tb=curth; curth=nxtth; nxtth=tb; tb=curtl; curtl=nxttl; nxttl=tb;
  }

  gemm_mm<<<dim3(KK/128, KK/128, BB), 512, MM_SMEM>>>(
      VAGh, VAGl, DD, (long)KK*DD, Sh, Sl, DD, 0L, SV, KK, ZK2,
      SVh, SVl, nullptr, nullptr, 0, DD, 3, EPI_PLAIN, 0, 0, 1.f,
      nullptr, nullptr, 0L, nullptr, 0L, nullptr);
  gemm_mm<<<dim3(KK/128, KK/128, BB), 512, MM_SMEM>>>(
      SVh, SVl, KK, ZK2, curth, curtl, KK, 0L, P2, KK, ZK2,
      P2h, P2l, nullptr, nullptr, 0, KK, 1, EPI_PLAIN, 0, 0, 1.f,
      nullptr, nullptr, 0L, nullptr, 0L, nullptr);
  gemm_mm<<<dim3(KK/128, KK/128, BB), 512, MM_SMEM>>>(
      P2h, P2l, KK, ZK2, ACth, ACtl, KK, 0L, R4, KK, ZK2,
      R4h, R4l, nullptr, nullptr, 0, KK, 3, EPI_RSUB, 0, 0, 1.f,
      nullptr, SV, ZK2, nullptr, 0L, nullptr);
  gemm_mm<<<dim3(KK/128, KK/128, BB), 512, MM_SMEM>>>(
      R4h, R4l, KK, ZK2, curth, curtl, KK, 0L, P2, KK, ZK2,
      P2h, P2l, nullptr, nullptr, 0, KK, 1, EPI_ADD, 0, 0, 1.f,
      nullptr, P2, ZK2, nullptr, 0L, nullptr);

  gemm_mm<<<dim3(DD/128, KK/128, BB), 512, MM_SMEM>>>(
      P2h, P2l, KK, ZK2, Sth, Stl, KK, 0L, outS, DD, (long)KK*DD,
      nullptr, nullptr, nullptr, nullptr, 0, KK, 3, EPI_SNEXT, 0, 0, 1.f,
      nullptr, S, 0L, VAG, (long)KK*DD, nullptr);

  // ---- topk + combine -> out ----
  topk_k<<<MBT, 128>>>(L, S, P_, BYP, out);
}